// round 9
// baseline (speedup 1.0000x reference)
#include <cuda_runtime.h>
#include <cuda_bf16.h>
#include <math.h>
#include <stdint.h>

#define D_MODEL 1024
#define N_HEADS 16
#define D_HEAD  64
#define BATCH   4
#define SEQ     2048
#define M_TOK   (BATCH * SEQ)     // 8192
#define QKV_N   (3 * D_MODEL)     // 3072
#define GK      1024
#define HB      (BATCH * N_HEADS) // 64

// ---------------------------------------------------------------------------
// Device-global scratch
// ---------------------------------------------------------------------------
__device__ __nv_bfloat16 g_xhi[(size_t)M_TOK * D_MODEL];
__device__ __nv_bfloat16 g_xlo[(size_t)M_TOK * D_MODEL];
__device__ __nv_bfloat16 g_wqkvT_hi[(size_t)QKV_N * D_MODEL];
__device__ __nv_bfloat16 g_wqkvT_lo[(size_t)QKV_N * D_MODEL];
__device__ __nv_bfloat16 g_woutT_hi[(size_t)D_MODEL * D_MODEL];
__device__ __nv_bfloat16 g_woutT_lo[(size_t)D_MODEL * D_MODEL];
// q/k/v split, head-contiguous: [(b*16+h)][t][64]
__device__ __nv_bfloat16 g_qhi[(size_t)HB * SEQ * D_HEAD];
__device__ __nv_bfloat16 g_qlo[(size_t)HB * SEQ * D_HEAD];
__device__ __nv_bfloat16 g_khi[(size_t)HB * SEQ * D_HEAD];
__device__ __nv_bfloat16 g_klo[(size_t)HB * SEQ * D_HEAD];
__device__ __nv_bfloat16 g_vhi[(size_t)HB * SEQ * D_HEAD];
__device__ __nv_bfloat16 g_vlo[(size_t)HB * SEQ * D_HEAD];
__device__ __nv_bfloat16 g_atthi[(size_t)M_TOK * D_MODEL];
__device__ __nv_bfloat16 g_attlo[(size_t)M_TOK * D_MODEL];

// ---------------------------------------------------------------------------
// Baseline-PTX helpers (compute_103 target: no tcgen05)
// ---------------------------------------------------------------------------
__device__ __forceinline__ uint32_t smem_u32(const void* p) {
    uint32_t a;
    asm("{ .reg .u64 t; cvta.to.shared.u64 t, %1; cvt.u32.u64 %0, t; }"
        : "=r"(a) : "l"(p));
    return a;
}
__device__ __forceinline__ void cp16(uint32_t dst, const void* src) {
    asm volatile("cp.async.cg.shared.global [%0], [%1], 16;"
                 :: "r"(dst), "l"(src) : "memory");
}
#define CP_COMMIT() asm volatile("cp.async.commit_group;" ::: "memory")
#define CP_WAIT(n)  asm volatile("cp.async.wait_group %0;" :: "n"(n) : "memory")

__device__ __forceinline__ void ldsm_x4(uint32_t* r, uint32_t addr) {
    asm volatile("ldmatrix.sync.aligned.m8n8.x4.shared.b16 {%0,%1,%2,%3}, [%4];"
                 : "=r"(r[0]), "=r"(r[1]), "=r"(r[2]), "=r"(r[3]) : "r"(addr));
}
__device__ __forceinline__ void ldsm_x4t(uint32_t* r, uint32_t addr) {
    asm volatile("ldmatrix.sync.aligned.m8n8.x4.trans.shared.b16 {%0,%1,%2,%3}, [%4];"
                 : "=r"(r[0]), "=r"(r[1]), "=r"(r[2]), "=r"(r[3]) : "r"(addr));
}
__device__ __forceinline__ void mma_bf16(float* d, const uint32_t* a, const uint32_t* b) {
    asm volatile(
        "mma.sync.aligned.m16n8k16.row.col.f32.bf16.bf16.f32 "
        "{%0,%1,%2,%3}, {%4,%5,%6,%7}, {%8,%9}, {%0,%1,%2,%3};"
        : "+f"(d[0]), "+f"(d[1]), "+f"(d[2]), "+f"(d[3])
        : "r"(a[0]), "r"(a[1]), "r"(a[2]), "r"(a[3]), "r"(b[0]), "r"(b[1]));
}
__device__ __forceinline__ float ex2f(float x) {
    float r;
    asm("ex2.approx.f32 %0, %1;" : "=f"(r) : "f"(x));
    return r;
}
#define SWZ128(o) ((o) ^ (((o) >> 3) & 0x70))
#define SWZ64(o)  ((o) ^ (((o) >> 3) & 0x30))

__device__ __forceinline__ uint32_t pack_bf2(__nv_bfloat16 a, __nv_bfloat16 b) {
    __nv_bfloat162 t(a, b);
    return *(uint32_t*)&t;
}

// ---------------------------------------------------------------------------
// Prep kernels
// ---------------------------------------------------------------------------
__global__ void split_x_kernel(const float* __restrict__ x) {
    size_t i = ((size_t)blockIdx.x * blockDim.x + threadIdx.x) * 4;
    if (i >= (size_t)M_TOK * D_MODEL) return;
    float4 v = *(const float4*)(x + i);
    __nv_bfloat16 h0 = __float2bfloat16(v.x), h1 = __float2bfloat16(v.y);
    __nv_bfloat16 h2 = __float2bfloat16(v.z), h3 = __float2bfloat16(v.w);
    __nv_bfloat162* hp = (__nv_bfloat162*)(g_xhi + i);
    __nv_bfloat162* lp = (__nv_bfloat162*)(g_xlo + i);
    hp[0] = __nv_bfloat162(h0, h1);
    hp[1] = __nv_bfloat162(h2, h3);
    lp[0] = __nv_bfloat162(__float2bfloat16(v.x - __bfloat162float(h0)),
                           __float2bfloat16(v.y - __bfloat162float(h1)));
    lp[1] = __nv_bfloat162(__float2bfloat16(v.z - __bfloat162float(h2)),
                           __float2bfloat16(v.w - __bfloat162float(h3)));
}

__device__ __forceinline__ void transpose_split_body(
    const float* __restrict__ W, __nv_bfloat16* __restrict__ Thi,
    __nv_bfloat16* __restrict__ Tlo, int K, int N)
{
    __shared__ float t[32][33];
    int tx = threadIdx.x, ty = threadIdx.y;
    int x = blockIdx.x * 32 + tx;
    int y0 = blockIdx.y * 32;
    #pragma unroll
    for (int j = 0; j < 32; j += 8)
        t[ty + j][tx] = W[(size_t)(y0 + ty + j) * N + x];
    __syncthreads();
    int xo = y0 + tx;
    int yo = blockIdx.x * 32;
    #pragma unroll
    for (int j = 0; j < 32; j += 8) {
        float v = t[tx][ty + j];
        __nv_bfloat16 h = __float2bfloat16(v);
        size_t o = (size_t)(yo + ty + j) * K + xo;
        Thi[o] = h;
        Tlo[o] = __float2bfloat16(v - __bfloat162float(h));
    }
}
__global__ void tr_wqkv_kernel(const float* __restrict__ W) {
    transpose_split_body(W, g_wqkvT_hi, g_wqkvT_lo, D_MODEL, QKV_N);
}
__global__ void tr_wout_kernel(const float* __restrict__ W) {
    transpose_split_body(W, g_woutT_hi, g_woutT_lo, D_MODEL, D_MODEL);
}

// ---------------------------------------------------------------------------
// GEMM (proven R6/R8 config): CTA 128x128, 4 warps (64x64), KC=32 (SW64),
// 3-stage cp.async ring, single barrier per k-step. 3-term split mma.
// ---------------------------------------------------------------------------
#define KC       32
#define TILE_B3  (128 * 64)          // 8KB: 128 rows x 64B
#define STAGE_B3 (4 * TILE_B3)       // 32KB: Ahi,Alo,Bhi,Blo
#define NSTEPS3  (GK / KC)           // 32

__device__ __forceinline__ void tile_loads3(
    uint32_t sbase, const __nv_bfloat16* __restrict__ g, int k0, int tid)
{
    #pragma unroll
    for (int j = 0; j < 4; j++) {
        int i = tid + j * 128;            // 0..511 chunk id (16B chunks)
        int r = i >> 2, c = i & 3;
        cp16(sbase + SWZ64(r * 64 + c * 16), g + (size_t)r * GK + k0 + c * 8);
    }
}

__device__ __forceinline__ void stage_loads3(
    uint32_t st,
    const __nv_bfloat16* gAh, const __nv_bfloat16* gAl,
    const __nv_bfloat16* gBh, const __nv_bfloat16* gBl, int k0, int tid)
{
    tile_loads3(st + 0 * TILE_B3, gAh, k0, tid);
    tile_loads3(st + 1 * TILE_B3, gAl, k0, tid);
    tile_loads3(st + 2 * TILE_B3, gBh, k0, tid);
    tile_loads3(st + 3 * TILE_B3, gBl, k0, tid);
}

// q pre-scale folds 1/sqrt(64) AND log2(e): softmax runs in log2 domain.
#define Q_PRESCALE 0.180336880f

__device__ __forceinline__ void write_qkv_pair(int row, int col, float v0, float v1) {
    int b = row >> 11, t = row & 2047;
    int which = col >> 10;
    int h = (col >> 6) & 15;
    int d = col & 63;
    if (which == 0) { v0 *= Q_PRESCALE; v1 *= Q_PRESCALE; }
    size_t off = (((size_t)((b << 4) + h) << 11) + (size_t)t) * D_HEAD + d;
    __nv_bfloat16 h0 = __float2bfloat16(v0), h1 = __float2bfloat16(v1);
    uint32_t hi = pack_bf2(h0, h1);
    uint32_t lo = pack_bf2(__float2bfloat16(v0 - __bfloat162float(h0)),
                           __float2bfloat16(v1 - __bfloat162float(h1)));
    __nv_bfloat16* dh = (which == 0) ? g_qhi : (which == 1) ? g_khi : g_vhi;
    __nv_bfloat16* dl = (which == 0) ? g_qlo : (which == 1) ? g_klo : g_vlo;
    *(uint32_t*)&dh[off] = hi;
    *(uint32_t*)&dl[off] = lo;
}

template <int MODE>
__device__ __forceinline__ void gemm_body(
    const __nv_bfloat16* __restrict__ Ahi, const __nv_bfloat16* __restrict__ Alo,
    const __nv_bfloat16* __restrict__ Bhi, const __nv_bfloat16* __restrict__ Blo,
    float* __restrict__ C, int Ntot)
{
    extern __shared__ char gsm[];
    const int tid  = threadIdx.x;
    const int wid  = tid >> 5, lane = tid & 31;
    const int cN   = blockIdx.x, cM = blockIdx.y;
    const int wm   = (wid & 1) * 64;
    const int wn   = (wid >> 1) * 64;

    const __nv_bfloat16* gAh = Ahi + (size_t)cM * 128 * GK;
    const __nv_bfloat16* gAl = Alo + (size_t)cM * 128 * GK;
    const __nv_bfloat16* gBh = Bhi + (size_t)cN * 128 * GK;
    const __nv_bfloat16* gBl = Blo + (size_t)cN * 128 * GK;

    const uint32_t smbase = smem_u32(gsm);

    float acc[4][8][4];
    #pragma unroll
    for (int mi = 0; mi < 4; mi++)
        #pragma unroll
        for (int nf = 0; nf < 8; nf++)
            #pragma unroll
            for (int e = 0; e < 4; e++) acc[mi][nf][e] = 0.f;

    const int aRow = wm + (lane & 15);
    const int aKof = (lane >> 4) * 16;
    const int bRow = wn + ((lane >> 4) << 3) + (lane & 7);
    const int bKof = ((lane >> 3) & 1) * 16;

    stage_loads3(smbase,            gAh, gAl, gBh, gBl, 0, tid);
    CP_COMMIT();
    stage_loads3(smbase + STAGE_B3, gAh, gAl, gBh, gBl, KC, tid);
    CP_COMMIT();

    for (int kc = 0; kc < NSTEPS3; kc++) {
        const int slot = kc % 3;
        if (kc + 1 < NSTEPS3) { CP_WAIT(1); } else { CP_WAIT(0); }
        __syncthreads();
        if (kc + 2 < NSTEPS3) {
            stage_loads3(smbase + ((kc + 2) % 3) * STAGE_B3,
                         gAh, gAl, gBh, gBl, (kc + 2) * KC, tid);
            CP_COMMIT();
        }

        const uint32_t sAh = smbase + slot * STAGE_B3;
        const uint32_t sAl = sAh + TILE_B3;
        const uint32_t sBh = sAh + 2 * TILE_B3;
        const uint32_t sBl = sAh + 3 * TILE_B3;

        #pragma unroll
        for (int kk = 0; kk < 2; kk++) {
            const int kb = kk * 32;
            uint32_t aH[4][4], aL[4][4], bH[4][4], bL[4][4];
            #pragma unroll
            for (int mi = 0; mi < 4; mi++) {
                uint32_t off = SWZ64((aRow + mi * 16) * 64 + kb + aKof);
                ldsm_x4(aH[mi], sAh + off);
                ldsm_x4(aL[mi], sAl + off);
            }
            #pragma unroll
            for (int g = 0; g < 4; g++) {
                uint32_t off = SWZ64((bRow + g * 16) * 64 + kb + bKof);
                ldsm_x4(bH[g], sBh + off);
                ldsm_x4(bL[g], sBl + off);
            }
            #pragma unroll
            for (int mi = 0; mi < 4; mi++)
                #pragma unroll
                for (int nf = 0; nf < 8; nf++) {
                    const uint32_t* bh = &bH[nf >> 1][(nf & 1) * 2];
                    const uint32_t* bl = &bL[nf >> 1][(nf & 1) * 2];
                    mma_bf16(acc[mi][nf], aH[mi], bh);
                    mma_bf16(acc[mi][nf], aH[mi], bl);
                    mma_bf16(acc[mi][nf], aL[mi], bh);
                }
        }
    }

    const int row0 = cM * 128 + wm + (lane >> 2);
    const int col0 = cN * 128 + wn + (lane & 3) * 2;
    #pragma unroll
    for (int mi = 0; mi < 4; mi++)
        #pragma unroll
        for (int nf = 0; nf < 8; nf++) {
            int r = row0 + mi * 16;
            int c = col0 + nf * 8;
            if (MODE == 0) {
                float* c0 = C + (size_t)r * Ntot + c;
                float* c1 = c0 + 8 * Ntot;
                *(float2*)c0 = make_float2(acc[mi][nf][0], acc[mi][nf][1]);
                *(float2*)c1 = make_float2(acc[mi][nf][2], acc[mi][nf][3]);
            } else {
                write_qkv_pair(r,     c, acc[mi][nf][0], acc[mi][nf][1]);
                write_qkv_pair(r + 8, c, acc[mi][nf][2], acc[mi][nf][3]);
            }
        }
}

__global__ __launch_bounds__(128, 2) void qkv_gemm2_kernel() {
    gemm_body<1>(g_xhi, g_xlo, g_wqkvT_hi, g_wqkvT_lo, nullptr, QKV_N);
}
__global__ __launch_bounds__(128, 2) void out_gemm2_kernel(float* __restrict__ out) {
    gemm_body<0>(g_atthi, g_attlo, g_woutT_hi, g_woutT_lo, out, D_MODEL);
}

// ---------------------------------------------------------------------------
// Tensor-core causal flash attention, split-bf16, 3-stage K/V ring,
// log2-domain softmax (ex2.approx), packed-bf16 max shuffles.
// CTA: 128 thr = 4 warps, 64 q rows (16/warp), BK=64 keys/iter.
// ---------------------------------------------------------------------------
#define AQ     64
#define AK     64
#define ATILE  8192                 // 64 rows x 128B
#define AQT    (SEQ / AQ)           // 32
#define AST    3                    // KV ring stages

__device__ __forceinline__ void load_tile64(
    uint32_t sbase, const __nv_bfloat16* __restrict__ g, int tid)
{
    #pragma unroll
    for (int j = 0; j < 4; j++) {
        int i = tid + j * 128;
        int r = i >> 3, c = i & 7;
        cp16(sbase + SWZ128(r * 128 + c * 16), g + (size_t)r * D_HEAD + c * 8);
    }
}
__device__ __forceinline__ void load_kv_stage(
    uint32_t st, size_t nb, int tid)
{
    load_tile64(st + 0 * ATILE, g_khi + nb, tid);
    load_tile64(st + 1 * ATILE, g_klo + nb, tid);
    load_tile64(st + 2 * ATILE, g_vhi + nb, tid);
    load_tile64(st + 3 * ATILE, g_vlo + nb, tid);
}

__global__ __launch_bounds__(128) void attn_tc_kernel()
{
    extern __shared__ char s_raw[];
    const int tid  = threadIdx.x;
    const int lane = tid & 31, wid = tid >> 5;
    const int qt = (AQT - 1) - blockIdx.x;   // long CTAs first
    const int hb = blockIdx.y;
    const int q0 = qt * AQ;
    const int wm = wid * 16;
    const int nst = qt + 1;                  // KV tiles this CTA consumes

    const uint32_t sb  = smem_u32(s_raw);
    const uint32_t sQh = sb, sQl = sb + ATILE;
    const uint32_t sKV = sb + 2 * ATILE;     // AST stages x {Khi,Klo,Vhi,Vlo}

    const size_t headBase = (size_t)hb * SEQ * D_HEAD;

    // Prologue: group0 = Q + stage0; group1 = stage1 (if any)
    load_tile64(sQh, g_qhi + headBase + (size_t)q0 * D_HEAD, tid);
    load_tile64(sQl, g_qlo + headBase + (size_t)q0 * D_HEAD, tid);
    load_kv_stage(sKV, headBase, tid);
    CP_COMMIT();
    int sc = 1;
    if (nst > 1) {
        load_kv_stage(sKV + 4 * ATILE, headBase + (size_t)AK * D_HEAD, tid);
        CP_COMMIT();
        sc = 2;
    }

    const int aRow = wm + (lane & 15);
    const int aKof = (lane >> 4) * 16;
    uint32_t Qh[4][4], Ql[4][4];

    const int bRow = ((lane >> 4) << 3) + (lane & 7);
    const int bKof = ((lane >> 3) & 1) * 16;
    const int vRow = lane & 15;
    const int vKof = (lane >> 4) * 16;

    float O[8][4];
    #pragma unroll
    for (int nd = 0; nd < 8; nd++)
        #pragma unroll
        for (int e = 0; e < 4; e++) O[nd][e] = 0.f;
    float m0 = -1e30f, m1 = -1e30f, l0 = 0.f, l1 = 0.f;

    const int qg0 = q0 + wm + (lane >> 2);
    const int qg1 = qg0 + 8;

    int cs = 0;
    for (int kb = 0; kb <= q0; kb += AK) {
        if (sc - cs >= 2) { CP_WAIT(1); } else { CP_WAIT(0); }
        __syncthreads();
        if (cs + 2 < nst) {          // prefetch stage cs+2 into slot sc%3
            load_kv_stage(sKV + (sc % AST) * 4 * ATILE,
                          headBase + (size_t)(cs + 2) * AK * D_HEAD, tid);
            CP_COMMIT();
            sc++;
        }
        if (cs == 0) {               // Q landed with group0
            #pragma unroll
            for (int kk = 0; kk < 4; kk++) {
                uint32_t off = SWZ128(aRow * 128 + kk * 32 + aKof);
                ldsm_x4(Qh[kk], sQh + off);
                ldsm_x4(Ql[kk], sQl + off);
            }
        }
        const uint32_t sKh = sKV + (cs % AST) * 4 * ATILE;
        cs++;
        const uint32_t sKl = sKh + ATILE;
        const uint32_t sVh = sKh + 2 * ATILE;
        const uint32_t sVl = sKh + 3 * ATILE;

        // ---- S = Q K^T (3-term split), log2 domain ----
        float S[8][4];
        #pragma unroll
        for (int nf = 0; nf < 8; nf++)
            #pragma unroll
            for (int e = 0; e < 4; e++) S[nf][e] = 0.f;

        #pragma unroll
        for (int kk = 0; kk < 4; kk++) {
            uint32_t Kh[4][4], Kl[4][4];
            #pragma unroll
            for (int g = 0; g < 4; g++) {
                uint32_t off = SWZ128((bRow + g * 16) * 128 + kk * 32 + bKof);
                ldsm_x4(Kh[g], sKh + off);
                ldsm_x4(Kl[g], sKl + off);
            }
            #pragma unroll
            for (int nf = 0; nf < 8; nf++) {
                const uint32_t* bh = &Kh[nf >> 1][(nf & 1) * 2];
                const uint32_t* bl = &Kl[nf >> 1][(nf & 1) * 2];
                mma_bf16(S[nf], Qh[kk], bh);
                mma_bf16(S[nf], Qh[kk], bl);
                mma_bf16(S[nf], Ql[kk], bh);
            }
        }

        if (kb == q0) {              // causal mask on diagonal tile
            #pragma unroll
            for (int nf = 0; nf < 8; nf++) {
                int kg = kb + nf * 8 + (lane & 3) * 2;
                if (kg     > qg0) S[nf][0] = -1e30f;
                if (kg + 1 > qg0) S[nf][1] = -1e30f;
                if (kg     > qg1) S[nf][2] = -1e30f;
                if (kg + 1 > qg1) S[nf][3] = -1e30f;
            }
        }

        // ---- online softmax (log2 domain) ----
        float rm0 = -1e30f, rm1 = -1e30f;
        #pragma unroll
        for (int nf = 0; nf < 8; nf++) {
            rm0 = fmaxf(rm0, fmaxf(S[nf][0], S[nf][1]));
            rm1 = fmaxf(rm1, fmaxf(S[nf][2], S[nf][3]));
        }
        // packed bf16x2 max across the quad (m is just a reference point)
        {
            __nv_bfloat162 pk = __floats2bfloat162_rn(rm0, rm1);
            uint32_t u = *(uint32_t*)&pk, o;
            o = __shfl_xor_sync(0xffffffff, u, 1);
            pk = __hmax2(pk, *(__nv_bfloat162*)&o);
            u = *(uint32_t*)&pk;
            o = __shfl_xor_sync(0xffffffff, u, 2);
            pk = __hmax2(pk, *(__nv_bfloat162*)&o);
            rm0 = __bfloat162float(pk.x);
            rm1 = __bfloat162float(pk.y);
        }

        float mn0 = fmaxf(m0, rm0), mn1 = fmaxf(m1, rm1);
        float c0 = ex2f(m0 - mn0), c1 = ex2f(m1 - mn1);
        m0 = mn0; m1 = mn1;

        float rs0 = 0.f, rs1 = 0.f;
        #pragma unroll
        for (int nf = 0; nf < 8; nf++) {
            S[nf][0] = ex2f(S[nf][0] - m0);
            S[nf][1] = ex2f(S[nf][1] - m0);
            S[nf][2] = ex2f(S[nf][2] - m1);
            S[nf][3] = ex2f(S[nf][3] - m1);
            rs0 += S[nf][0] + S[nf][1];
            rs1 += S[nf][2] + S[nf][3];
        }
        rs0 += __shfl_xor_sync(0xffffffff, rs0, 1);
        rs0 += __shfl_xor_sync(0xffffffff, rs0, 2);
        rs1 += __shfl_xor_sync(0xffffffff, rs1, 1);
        rs1 += __shfl_xor_sync(0xffffffff, rs1, 2);
        l0 = l0 * c0 + rs0;
        l1 = l1 * c1 + rs1;

        #pragma unroll
        for (int nd = 0; nd < 8; nd++) {
            O[nd][0] *= c0; O[nd][1] *= c0;
            O[nd][2] *= c1; O[nd][3] *= c1;
        }

        // ---- O += P V (3-term split) ----
        #pragma unroll
        for (int kk = 0; kk < 4; kk++) {
            uint32_t Vh[4][4], Vl[4][4];
            #pragma unroll
            for (int gd = 0; gd < 4; gd++) {
                uint32_t off = SWZ128((kk * 16 + vRow) * 128 + gd * 32 + vKof);
                ldsm_x4t(Vh[gd], sVh + off);
                ldsm_x4t(Vl[gd], sVl + off);
            }
            const float* p0 = S[2 * kk];
            const float* p1 = S[2 * kk + 1];
            uint32_t ah[4], al[4];
            {
                __nv_bfloat16 h00 = __float2bfloat16(p0[0]), h01 = __float2bfloat16(p0[1]);
                __nv_bfloat16 h02 = __float2bfloat16(p0[2]), h03 = __float2bfloat16(p0[3]);
                __nv_bfloat16 h10 = __float2bfloat16(p1[0]), h11 = __float2bfloat16(p1[1]);
                __nv_bfloat16 h12 = __float2bfloat16(p1[2]), h13 = __float2bfloat16(p1[3]);
                ah[0] = pack_bf2(h00, h01);
                ah[1] = pack_bf2(h02, h03);
                ah[2] = pack_bf2(h10, h11);
                ah[3] = pack_bf2(h12, h13);
                al[0] = pack_bf2(__float2bfloat16(p0[0] - __bfloat162float(h00)),
                                 __float2bfloat16(p0[1] - __bfloat162float(h01)));
                al[1] = pack_bf2(__float2bfloat16(p0[2] - __bfloat162float(h02)),
                                 __float2bfloat16(p0[3] - __bfloat162float(h03)));
                al[2] = pack_bf2(__float2bfloat16(p1[0] - __bfloat162float(h10)),
                                 __float2bfloat16(p1[1] - __bfloat162float(h11)));
                al[3] = pack_bf2(__float2bfloat16(p1[2] - __bfloat162float(h12)),
                                 __float2bfloat16(p1[3] - __bfloat162float(h13)));
            }
            #pragma unroll
            for (int nd = 0; nd < 8; nd++) {
                const uint32_t* bh = &Vh[nd >> 1][(nd & 1) * 2];
                const uint32_t* bl = &Vl[nd >> 1][(nd & 1) * 2];
                mma_bf16(O[nd], ah, bh);
                mma_bf16(O[nd], ah, bl);
                mma_bf16(O[nd], al, bh);
            }
        }
    }

    const float inv0 = 1.f / l0, inv1 = 1.f / l1;
    const int b = hb >> 4, h = hb & 15;
    const size_t base0 = ((size_t)(b * SEQ + qg0)) * D_MODEL + h * D_HEAD;
    const size_t base1 = ((size_t)(b * SEQ + qg1)) * D_MODEL + h * D_HEAD;
    #pragma unroll
    for (int nd = 0; nd < 8; nd++) {
        int d = nd * 8 + (lane & 3) * 2;
        float v0 = O[nd][0] * inv0, v1 = O[nd][1] * inv0;
        float v2 = O[nd][2] * inv1, v3 = O[nd][3] * inv1;
        __nv_bfloat16 h0 = __float2bfloat16(v0), h1 = __float2bfloat16(v1);
        __nv_bfloat16 h2 = __float2bfloat16(v2), h3 = __float2bfloat16(v3);
        *(uint32_t*)&g_atthi[base0 + d] = pack_bf2(h0, h1);
        *(uint32_t*)&g_attlo[base0 + d] =
            pack_bf2(__float2bfloat16(v0 - __bfloat162float(h0)),
                     __float2bfloat16(v1 - __bfloat162float(h1)));
        *(uint32_t*)&g_atthi[base1 + d] = pack_bf2(h2, h3);
        *(uint32_t*)&g_attlo[base1 + d] =
            pack_bf2(__float2bfloat16(v2 - __bfloat162float(h2)),
                     __float2bfloat16(v3 - __bfloat162float(h3)));
    }
}

// ---------------------------------------------------------------------------
extern "C" void kernel_launch(void* const* d_in, const int* in_sizes, int n_in,
                              void* d_out, int out_size)
{
    const float* x     = (const float*)d_in[0];
    const float* W_qkv = (const float*)d_in[1];
    const float* W_out = (const float*)d_in[2];
    float* out = (float*)d_out;

    const int gemm_smem = 3 * STAGE_B3;                  // 96 KB
    const int attn_smem = 2 * ATILE + AST * 4 * ATILE;   // 112 KB
    cudaFuncSetAttribute(qkv_gemm2_kernel,
                         cudaFuncAttributeMaxDynamicSharedMemorySize, gemm_smem);
    cudaFuncSetAttribute(out_gemm2_kernel,
                         cudaFuncAttributeMaxDynamicSharedMemorySize, gemm_smem);
    cudaFuncSetAttribute(attn_tc_kernel,
                         cudaFuncAttributeMaxDynamicSharedMemorySize, attn_smem);

    // 0) Input split / weight transposes
    {
        size_t n4 = (size_t)M_TOK * D_MODEL / 4;
        split_x_kernel<<<(unsigned)((n4 + 255) / 256), 256>>>(x);
        dim3 blk(32, 8);
        tr_wqkv_kernel<<<dim3(QKV_N / 32, D_MODEL / 32), blk>>>(W_qkv);
        tr_wout_kernel<<<dim3(D_MODEL / 32, D_MODEL / 32), blk>>>(W_out);
    }
    // 1) QKV projection -> split q/k/v (head-contiguous, q pre-scaled w/ log2e)
    qkv_gemm2_kernel<<<dim3(QKV_N / 128, M_TOK / 128), 128, gemm_smem>>>();
    // 2) Tensor-core causal flash attention -> g_att{hi,lo}
    attn_tc_kernel<<<dim3(AQT, HB), 128, attn_smem>>>();
    // 3) Output projection -> out (fp32)
    out_gemm2_kernel<<<dim3(D_MODEL / 128, M_TOK / 128), 128, gemm_smem>>>(out);
}

// round 10
// speedup vs baseline: 1.2716x; 1.2716x over previous
#include <cuda_runtime.h>
#include <cuda_bf16.h>
#include <cuda_fp16.h>
#include <math.h>
#include <stdint.h>

#define D_MODEL 1024
#define N_HEADS 16
#define D_HEAD  64
#define BATCH   4
#define SEQ     2048
#define M_TOK   (BATCH * SEQ)     // 8192
#define QKV_N   (3 * D_MODEL)     // 3072
#define QK_N    (2 * D_MODEL)     // 2048 (q,k columns)
#define GK      1024
#define HB      (BATCH * N_HEADS) // 64

// ---------------------------------------------------------------------------
// Device-global scratch
// ---------------------------------------------------------------------------
__device__ __nv_bfloat16 g_xhi[(size_t)M_TOK * D_MODEL];
__device__ __nv_bfloat16 g_xlo[(size_t)M_TOK * D_MODEL];
__device__ __half        g_xf16[(size_t)M_TOK * D_MODEL];
__device__ __nv_bfloat16 g_wqkvT_hi[(size_t)QKV_N * D_MODEL];
__device__ __nv_bfloat16 g_wqkvT_lo[(size_t)QKV_N * D_MODEL];
__device__ __half        g_wqkvT_f16[(size_t)QKV_N * D_MODEL];
__device__ __nv_bfloat16 g_woutT_hi[(size_t)D_MODEL * D_MODEL];
__device__ __nv_bfloat16 g_woutT_lo[(size_t)D_MODEL * D_MODEL];
// q/k split bf16 + v single fp16, head-contiguous: [(b*16+h)][t][64]
__device__ __nv_bfloat16 g_qhi[(size_t)HB * SEQ * D_HEAD];
__device__ __nv_bfloat16 g_qlo[(size_t)HB * SEQ * D_HEAD];
__device__ __nv_bfloat16 g_khi[(size_t)HB * SEQ * D_HEAD];
__device__ __nv_bfloat16 g_klo[(size_t)HB * SEQ * D_HEAD];
__device__ __half        g_vf16[(size_t)HB * SEQ * D_HEAD];
__device__ __nv_bfloat16 g_atthi[(size_t)M_TOK * D_MODEL];
__device__ __nv_bfloat16 g_attlo[(size_t)M_TOK * D_MODEL];

// ---------------------------------------------------------------------------
// Baseline-PTX helpers (compute_103 target: no tcgen05)
// ---------------------------------------------------------------------------
__device__ __forceinline__ uint32_t smem_u32(const void* p) {
    uint32_t a;
    asm("{ .reg .u64 t; cvta.to.shared.u64 t, %1; cvt.u32.u64 %0, t; }"
        : "=r"(a) : "l"(p));
    return a;
}
__device__ __forceinline__ void cp16(uint32_t dst, const void* src) {
    asm volatile("cp.async.cg.shared.global [%0], [%1], 16;"
                 :: "r"(dst), "l"(src) : "memory");
}
#define CP_COMMIT() asm volatile("cp.async.commit_group;" ::: "memory")
#define CP_WAIT(n)  asm volatile("cp.async.wait_group %0;" :: "n"(n) : "memory")

__device__ __forceinline__ void ldsm_x4(uint32_t* r, uint32_t addr) {
    asm volatile("ldmatrix.sync.aligned.m8n8.x4.shared.b16 {%0,%1,%2,%3}, [%4];"
                 : "=r"(r[0]), "=r"(r[1]), "=r"(r[2]), "=r"(r[3]) : "r"(addr));
}
__device__ __forceinline__ void ldsm_x4t(uint32_t* r, uint32_t addr) {
    asm volatile("ldmatrix.sync.aligned.m8n8.x4.trans.shared.b16 {%0,%1,%2,%3}, [%4];"
                 : "=r"(r[0]), "=r"(r[1]), "=r"(r[2]), "=r"(r[3]) : "r"(addr));
}
__device__ __forceinline__ void mma_bf16(float* d, const uint32_t* a, const uint32_t* b) {
    asm volatile(
        "mma.sync.aligned.m16n8k16.row.col.f32.bf16.bf16.f32 "
        "{%0,%1,%2,%3}, {%4,%5,%6,%7}, {%8,%9}, {%0,%1,%2,%3};"
        : "+f"(d[0]), "+f"(d[1]), "+f"(d[2]), "+f"(d[3])
        : "r"(a[0]), "r"(a[1]), "r"(a[2]), "r"(a[3]), "r"(b[0]), "r"(b[1]));
}
__device__ __forceinline__ void mma_f16(float* d, const uint32_t* a, const uint32_t* b) {
    asm volatile(
        "mma.sync.aligned.m16n8k16.row.col.f32.f16.f16.f32 "
        "{%0,%1,%2,%3}, {%4,%5,%6,%7}, {%8,%9}, {%0,%1,%2,%3};"
        : "+f"(d[0]), "+f"(d[1]), "+f"(d[2]), "+f"(d[3])
        : "r"(a[0]), "r"(a[1]), "r"(a[2]), "r"(a[3]), "r"(b[0]), "r"(b[1]));
}
__device__ __forceinline__ float ex2f(float x) {
    float r;
    asm("ex2.approx.f32 %0, %1;" : "=f"(r) : "f"(x));
    return r;
}
#define SWZ128(o) ((o) ^ (((o) >> 3) & 0x70))
#define SWZ64(o)  ((o) ^ (((o) >> 3) & 0x30))

__device__ __forceinline__ uint32_t pack_bf2(__nv_bfloat16 a, __nv_bfloat16 b) {
    __nv_bfloat162 t(a, b);
    return *(uint32_t*)&t;
}
__device__ __forceinline__ uint32_t pack_hf2(float a, float b) {
    __half2 t = __floats2half2_rn(a, b);
    return *(uint32_t*)&t;
}

// ---------------------------------------------------------------------------
// Prep kernels
// ---------------------------------------------------------------------------
__global__ void split_x_kernel(const float* __restrict__ x) {
    size_t i = ((size_t)blockIdx.x * blockDim.x + threadIdx.x) * 4;
    if (i >= (size_t)M_TOK * D_MODEL) return;
    float4 v = *(const float4*)(x + i);
    __nv_bfloat16 h0 = __float2bfloat16(v.x), h1 = __float2bfloat16(v.y);
    __nv_bfloat16 h2 = __float2bfloat16(v.z), h3 = __float2bfloat16(v.w);
    __nv_bfloat162* hp = (__nv_bfloat162*)(g_xhi + i);
    __nv_bfloat162* lp = (__nv_bfloat162*)(g_xlo + i);
    hp[0] = __nv_bfloat162(h0, h1);
    hp[1] = __nv_bfloat162(h2, h3);
    lp[0] = __nv_bfloat162(__float2bfloat16(v.x - __bfloat162float(h0)),
                           __float2bfloat16(v.y - __bfloat162float(h1)));
    lp[1] = __nv_bfloat162(__float2bfloat16(v.z - __bfloat162float(h2)),
                           __float2bfloat16(v.w - __bfloat162float(h3)));
    __half2* fp = (__half2*)(g_xf16 + i);
    fp[0] = __floats2half2_rn(v.x, v.y);
    fp[1] = __floats2half2_rn(v.z, v.w);
}

// W [K][N] -> T hi/lo bf16 [N][K] (+ optional fp16 single)
__device__ __forceinline__ void transpose_split_body(
    const float* __restrict__ W, __nv_bfloat16* __restrict__ Thi,
    __nv_bfloat16* __restrict__ Tlo, __half* __restrict__ Tf16, int K, int N)
{
    __shared__ float t[32][33];
    int tx = threadIdx.x, ty = threadIdx.y;
    int x = blockIdx.x * 32 + tx;
    int y0 = blockIdx.y * 32;
    #pragma unroll
    for (int j = 0; j < 32; j += 8)
        t[ty + j][tx] = W[(size_t)(y0 + ty + j) * N + x];
    __syncthreads();
    int xo = y0 + tx;
    int yo = blockIdx.x * 32;
    #pragma unroll
    for (int j = 0; j < 32; j += 8) {
        float v = t[tx][ty + j];
        __nv_bfloat16 h = __float2bfloat16(v);
        size_t o = (size_t)(yo + ty + j) * K + xo;
        Thi[o] = h;
        Tlo[o] = __float2bfloat16(v - __bfloat162float(h));
        if (Tf16) Tf16[o] = __float2half_rn(v);
    }
}
__global__ void tr_wqkv_kernel(const float* __restrict__ W) {
    transpose_split_body(W, g_wqkvT_hi, g_wqkvT_lo, g_wqkvT_f16, D_MODEL, QKV_N);
}
__global__ void tr_wout_kernel(const float* __restrict__ W) {
    transpose_split_body(W, g_woutT_hi, g_woutT_lo, nullptr, D_MODEL, D_MODEL);
}

// ---------------------------------------------------------------------------
// 3-term split-bf16 GEMM (proven R8 config): CTA 128x128, 4 warps (64x64),
// KC=32 (SW64), 3-stage ring, single barrier per k-step.
// MODE 0: fp32 C. MODE 1: split-write q/k head-contiguous (cols < 2048).
// ---------------------------------------------------------------------------
#define KC       32
#define TILE_B3  (128 * 64)          // 8KB: 128 rows x 64B
#define STAGE_B3 (4 * TILE_B3)       // 32KB: Ahi,Alo,Bhi,Blo
#define NSTEPS3  (GK / KC)           // 32

__device__ __forceinline__ void tile_loads3(
    uint32_t sbase, const __nv_bfloat16* __restrict__ g, int k0, int tid)
{
    #pragma unroll
    for (int j = 0; j < 4; j++) {
        int i = tid + j * 128;            // 0..511 chunk id (16B chunks)
        int r = i >> 2, c = i & 3;
        cp16(sbase + SWZ64(r * 64 + c * 16), g + (size_t)r * GK + k0 + c * 8);
    }
}

__device__ __forceinline__ void stage_loads3(
    uint32_t st,
    const __nv_bfloat16* gAh, const __nv_bfloat16* gAl,
    const __nv_bfloat16* gBh, const __nv_bfloat16* gBl, int k0, int tid)
{
    tile_loads3(st + 0 * TILE_B3, gAh, k0, tid);
    tile_loads3(st + 1 * TILE_B3, gAl, k0, tid);
    tile_loads3(st + 2 * TILE_B3, gBh, k0, tid);
    tile_loads3(st + 3 * TILE_B3, gBl, k0, tid);
}

// q pre-scale folds 1/sqrt(64) AND log2(e): softmax runs in log2 domain.
#define Q_PRESCALE 0.180336880f

__device__ __forceinline__ void write_qk_pair(int row, int col, float v0, float v1) {
    int b = row >> 11, t = row & 2047;
    int which = col >> 10;               // 0 = q, 1 = k
    int h = (col >> 6) & 15;
    int d = col & 63;
    if (which == 0) { v0 *= Q_PRESCALE; v1 *= Q_PRESCALE; }
    size_t off = (((size_t)((b << 4) + h) << 11) + (size_t)t) * D_HEAD + d;
    __nv_bfloat16 h0 = __float2bfloat16(v0), h1 = __float2bfloat16(v1);
    uint32_t hi = pack_bf2(h0, h1);
    uint32_t lo = pack_bf2(__float2bfloat16(v0 - __bfloat162float(h0)),
                           __float2bfloat16(v1 - __bfloat162float(h1)));
    __nv_bfloat16* dh = (which == 0) ? g_qhi : g_khi;
    __nv_bfloat16* dl = (which == 0) ? g_qlo : g_klo;
    *(uint32_t*)&dh[off] = hi;
    *(uint32_t*)&dl[off] = lo;
}

template <int MODE>
__device__ __forceinline__ void gemm_body(
    const __nv_bfloat16* __restrict__ Ahi, const __nv_bfloat16* __restrict__ Alo,
    const __nv_bfloat16* __restrict__ Bhi, const __nv_bfloat16* __restrict__ Blo,
    float* __restrict__ C, int Ntot)
{
    extern __shared__ char gsm[];
    const int tid  = threadIdx.x;
    const int wid  = tid >> 5, lane = tid & 31;
    const int cN   = blockIdx.x, cM = blockIdx.y;
    const int wm   = (wid & 1) * 64;
    const int wn   = (wid >> 1) * 64;

    const __nv_bfloat16* gAh = Ahi + (size_t)cM * 128 * GK;
    const __nv_bfloat16* gAl = Alo + (size_t)cM * 128 * GK;
    const __nv_bfloat16* gBh = Bhi + (size_t)cN * 128 * GK;
    const __nv_bfloat16* gBl = Blo + (size_t)cN * 128 * GK;

    const uint32_t smbase = smem_u32(gsm);

    float acc[4][8][4];
    #pragma unroll
    for (int mi = 0; mi < 4; mi++)
        #pragma unroll
        for (int nf = 0; nf < 8; nf++)
            #pragma unroll
            for (int e = 0; e < 4; e++) acc[mi][nf][e] = 0.f;

    const int aRow = wm + (lane & 15);
    const int aKof = (lane >> 4) * 16;
    const int bRow = wn + ((lane >> 4) << 3) + (lane & 7);
    const int bKof = ((lane >> 3) & 1) * 16;

    stage_loads3(smbase,            gAh, gAl, gBh, gBl, 0, tid);
    CP_COMMIT();
    stage_loads3(smbase + STAGE_B3, gAh, gAl, gBh, gBl, KC, tid);
    CP_COMMIT();

    for (int kc = 0; kc < NSTEPS3; kc++) {
        const int slot = kc % 3;
        if (kc + 1 < NSTEPS3) { CP_WAIT(1); } else { CP_WAIT(0); }
        __syncthreads();
        if (kc + 2 < NSTEPS3) {
            stage_loads3(smbase + ((kc + 2) % 3) * STAGE_B3,
                         gAh, gAl, gBh, gBl, (kc + 2) * KC, tid);
            CP_COMMIT();
        }

        const uint32_t sAh = smbase + slot * STAGE_B3;
        const uint32_t sAl = sAh + TILE_B3;
        const uint32_t sBh = sAh + 2 * TILE_B3;
        const uint32_t sBl = sAh + 3 * TILE_B3;

        #pragma unroll
        for (int kk = 0; kk < 2; kk++) {
            const int kb = kk * 32;
            uint32_t aH[4][4], aL[4][4], bH[4][4], bL[4][4];
            #pragma unroll
            for (int mi = 0; mi < 4; mi++) {
                uint32_t off = SWZ64((aRow + mi * 16) * 64 + kb + aKof);
                ldsm_x4(aH[mi], sAh + off);
                ldsm_x4(aL[mi], sAl + off);
            }
            #pragma unroll
            for (int g = 0; g < 4; g++) {
                uint32_t off = SWZ64((bRow + g * 16) * 64 + kb + bKof);
                ldsm_x4(bH[g], sBh + off);
                ldsm_x4(bL[g], sBl + off);
            }
            #pragma unroll
            for (int mi = 0; mi < 4; mi++)
                #pragma unroll
                for (int nf = 0; nf < 8; nf++) {
                    const uint32_t* bh = &bH[nf >> 1][(nf & 1) * 2];
                    const uint32_t* bl = &bL[nf >> 1][(nf & 1) * 2];
                    mma_bf16(acc[mi][nf], aH[mi], bh);
                    mma_bf16(acc[mi][nf], aH[mi], bl);
                    mma_bf16(acc[mi][nf], aL[mi], bh);
                }
        }
    }

    const int row0 = cM * 128 + wm + (lane >> 2);
    const int col0 = cN * 128 + wn + (lane & 3) * 2;
    #pragma unroll
    for (int mi = 0; mi < 4; mi++)
        #pragma unroll
        for (int nf = 0; nf < 8; nf++) {
            int r = row0 + mi * 16;
            int c = col0 + nf * 8;
            if (MODE == 0) {
                float* c0 = C + (size_t)r * Ntot + c;
                float* c1 = c0 + 8 * Ntot;
                *(float2*)c0 = make_float2(acc[mi][nf][0], acc[mi][nf][1]);
                *(float2*)c1 = make_float2(acc[mi][nf][2], acc[mi][nf][3]);
            } else {
                write_qk_pair(r,     c, acc[mi][nf][0], acc[mi][nf][1]);
                write_qk_pair(r + 8, c, acc[mi][nf][2], acc[mi][nf][3]);
            }
        }
}

__global__ __launch_bounds__(128, 2) void qk_gemm_kernel() {
    gemm_body<1>(g_xhi, g_xlo, g_wqkvT_hi, g_wqkvT_lo, nullptr, QK_N);
}
__global__ __launch_bounds__(128, 2) void out_gemm2_kernel(float* __restrict__ out) {
    gemm_body<0>(g_atthi, g_attlo, g_woutT_hi, g_woutT_lo, out, D_MODEL);
}

// ---------------------------------------------------------------------------
// v-GEMM: single-term fp16. A = x_f16 [M][1024], B = W_qkv^T f16 rows
// [2048+cN*128 ..][1024]. CTA 128x128, 4 warps (64x64), KC=32, 3-stage ring.
// Writes v fp16 head-contiguous.
// ---------------------------------------------------------------------------
#define VSTAGE_B (2 * TILE_B3)       // 16KB: A,B

__global__ __launch_bounds__(128, 2) void v_gemm_kernel()
{
    extern __shared__ char gsm[];
    const int tid  = threadIdx.x;
    const int wid  = tid >> 5, lane = tid & 31;
    const int cN   = blockIdx.x, cM = blockIdx.y;
    const int wm   = (wid & 1) * 64;
    const int wn   = (wid >> 1) * 64;

    const __nv_bfloat16* gA = (const __nv_bfloat16*)(g_xf16 + (size_t)cM * 128 * GK);
    const __nv_bfloat16* gB = (const __nv_bfloat16*)(g_wqkvT_f16 +
                               (size_t)(QK_N + cN * 128) * GK);

    const uint32_t smbase = smem_u32(gsm);

    float acc[4][8][4];
    #pragma unroll
    for (int mi = 0; mi < 4; mi++)
        #pragma unroll
        for (int nf = 0; nf < 8; nf++)
            #pragma unroll
            for (int e = 0; e < 4; e++) acc[mi][nf][e] = 0.f;

    const int aRow = wm + (lane & 15);
    const int aKof = (lane >> 4) * 16;
    const int bRow = wn + ((lane >> 4) << 3) + (lane & 7);
    const int bKof = ((lane >> 3) & 1) * 16;

    tile_loads3(smbase,              gA, 0, tid);
    tile_loads3(smbase + TILE_B3,    gB, 0, tid);
    CP_COMMIT();
    tile_loads3(smbase + VSTAGE_B,           gA, KC, tid);
    tile_loads3(smbase + VSTAGE_B + TILE_B3, gB, KC, tid);
    CP_COMMIT();

    for (int kc = 0; kc < NSTEPS3; kc++) {
        const int slot = kc % 3;
        if (kc + 1 < NSTEPS3) { CP_WAIT(1); } else { CP_WAIT(0); }
        __syncthreads();
        if (kc + 2 < NSTEPS3) {
            uint32_t st = smbase + ((kc + 2) % 3) * VSTAGE_B;
            tile_loads3(st,           gA, (kc + 2) * KC, tid);
            tile_loads3(st + TILE_B3, gB, (kc + 2) * KC, tid);
            CP_COMMIT();
        }

        const uint32_t sA = smbase + slot * VSTAGE_B;
        const uint32_t sB = sA + TILE_B3;

        #pragma unroll
        for (int kk = 0; kk < 2; kk++) {
            const int kb = kk * 32;
            uint32_t a[4][4], b[4][4];
            #pragma unroll
            for (int mi = 0; mi < 4; mi++)
                ldsm_x4(a[mi], sA + SWZ64((aRow + mi * 16) * 64 + kb + aKof));
            #pragma unroll
            for (int g = 0; g < 4; g++)
                ldsm_x4(b[g], sB + SWZ64((bRow + g * 16) * 64 + kb + bKof));
            #pragma unroll
            for (int mi = 0; mi < 4; mi++)
                #pragma unroll
                for (int nf = 0; nf < 8; nf++)
                    mma_f16(acc[mi][nf], a[mi], &b[nf >> 1][(nf & 1) * 2]);
        }
    }

    // Epilogue: write v fp16, head-contiguous
    const int row0 = cM * 128 + wm + (lane >> 2);
    const int col0 = cN * 128 + wn + (lane & 3) * 2;
    #pragma unroll
    for (int mi = 0; mi < 4; mi++)
        #pragma unroll
        for (int nf = 0; nf < 8; nf++) {
            int c = col0 + nf * 8;
            int h = c >> 6, d = c & 63;
            #pragma unroll
            for (int rr = 0; rr < 2; rr++) {
                int r = row0 + mi * 16 + rr * 8;
                int b = r >> 11, t = r & 2047;
                size_t off = (((size_t)((b << 4) + h) << 11) + (size_t)t) * D_HEAD + d;
                *(uint32_t*)&g_vf16[off] =
                    pack_hf2(acc[mi][nf][rr * 2], acc[mi][nf][rr * 2 + 1]);
            }
        }
}

// ---------------------------------------------------------------------------
// Tensor-core causal flash attention: S = 3-term bf16 split (q,k precision-
// critical), PV = single fp16 (P fp16 x V fp16). 2-stage K/V, log2 softmax.
// CTA: 128 thr = 4 warps, 64 q rows (16/warp), BK=64 keys/iter.
// ---------------------------------------------------------------------------
#define AQ     64
#define AK     64
#define ATILE  8192                 // 64 rows x 128B
#define AQT    (SEQ / AQ)           // 32
#define KVST   (3 * ATILE)          // stage: Khi, Klo, Vf16

__device__ __forceinline__ void load_tile64(
    uint32_t sbase, const void* __restrict__ g, int tid)
{
    #pragma unroll
    for (int j = 0; j < 4; j++) {
        int i = tid + j * 128;
        int r = i >> 3, c = i & 7;
        cp16(sbase + SWZ128(r * 128 + c * 16),
             (const __nv_bfloat16*)g + (size_t)r * D_HEAD + c * 8);
    }
}
__device__ __forceinline__ void load_kv_stage(uint32_t st, size_t nb, int tid)
{
    load_tile64(st + 0 * ATILE, g_khi + nb, tid);
    load_tile64(st + 1 * ATILE, g_klo + nb, tid);
    load_tile64(st + 2 * ATILE, g_vf16 + nb, tid);
}

__global__ __launch_bounds__(128) void attn_tc_kernel()
{
    extern __shared__ char s_raw[];
    const int tid  = threadIdx.x;
    const int lane = tid & 31, wid = tid >> 5;
    const int qt = (AQT - 1) - blockIdx.x;   // long CTAs first
    const int hb = blockIdx.y;
    const int q0 = qt * AQ;
    const int wm = wid * 16;

    const uint32_t sb  = smem_u32(s_raw);
    const uint32_t sQh = sb, sQl = sb + ATILE;
    const uint32_t sKV = sb + 2 * ATILE;     // 2 stages x {Khi,Klo,Vf16}

    const size_t headBase = (size_t)hb * SEQ * D_HEAD;

    // Prologue: Q and stage0 K/V
    load_tile64(sQh, g_qhi + headBase + (size_t)q0 * D_HEAD, tid);
    load_tile64(sQl, g_qlo + headBase + (size_t)q0 * D_HEAD, tid);
    CP_COMMIT();
    load_kv_stage(sKV, headBase, tid);
    CP_COMMIT();
    CP_WAIT(0);
    __syncthreads();

    const int aRow = wm + (lane & 15);
    const int aKof = (lane >> 4) * 16;
    uint32_t Qh[4][4], Ql[4][4];
    #pragma unroll
    for (int kk = 0; kk < 4; kk++) {
        uint32_t off = SWZ128(aRow * 128 + kk * 32 + aKof);
        ldsm_x4(Qh[kk], sQh + off);
        ldsm_x4(Ql[kk], sQl + off);
    }

    const int bRow = ((lane >> 4) << 3) + (lane & 7);
    const int bKof = ((lane >> 3) & 1) * 16;
    const int vRow = lane & 15;
    const int vKof = (lane >> 4) * 16;

    float O[8][4];
    #pragma unroll
    for (int nd = 0; nd < 8; nd++)
        #pragma unroll
        for (int e = 0; e < 4; e++) O[nd][e] = 0.f;
    float m0 = -1e30f, m1 = -1e30f, l0 = 0.f, l1 = 0.f;

    const int qg0 = q0 + wm + (lane >> 2);
    const int qg1 = qg0 + 8;

    for (int kb = 0; kb <= q0; kb += AK) {
        const int stage = (kb >> 6) & 1;
        if (kb > 0) {
            CP_WAIT(0);
            __syncthreads();
        }
        if (kb + AK <= q0) {     // prefetch next stage
            load_kv_stage(sKV + (stage ^ 1) * KVST,
                          headBase + (size_t)(kb + AK) * D_HEAD, tid);
            CP_COMMIT();
        }

        const uint32_t sKh = sKV + stage * KVST;
        const uint32_t sKl = sKh + ATILE;
        const uint32_t sVf = sKh + 2 * ATILE;

        // ---- S = Q K^T (3-term split), log2 domain ----
        float S[8][4];
        #pragma unroll
        for (int nf = 0; nf < 8; nf++)
            #pragma unroll
            for (int e = 0; e < 4; e++) S[nf][e] = 0.f;

        #pragma unroll
        for (int kk = 0; kk < 4; kk++) {
            uint32_t Kh[4][4], Kl[4][4];
            #pragma unroll
            for (int g = 0; g < 4; g++) {
                uint32_t off = SWZ128((bRow + g * 16) * 128 + kk * 32 + bKof);
                ldsm_x4(Kh[g], sKh + off);
                ldsm_x4(Kl[g], sKl + off);
            }
            #pragma unroll
            for (int nf = 0; nf < 8; nf++) {
                const uint32_t* bh = &Kh[nf >> 1][(nf & 1) * 2];
                const uint32_t* bl = &Kl[nf >> 1][(nf & 1) * 2];
                mma_bf16(S[nf], Qh[kk], bh);
                mma_bf16(S[nf], Qh[kk], bl);
                mma_bf16(S[nf], Ql[kk], bh);
            }
        }

        if (kb == q0) {              // causal mask on diagonal tile
            #pragma unroll
            for (int nf = 0; nf < 8; nf++) {
                int kg = kb + nf * 8 + (lane & 3) * 2;
                if (kg     > qg0) S[nf][0] = -1e30f;
                if (kg + 1 > qg0) S[nf][1] = -1e30f;
                if (kg     > qg1) S[nf][2] = -1e30f;
                if (kg + 1 > qg1) S[nf][3] = -1e30f;
            }
        }

        // ---- online softmax (log2 domain) ----
        float rm0 = -1e30f, rm1 = -1e30f;
        #pragma unroll
        for (int nf = 0; nf < 8; nf++) {
            rm0 = fmaxf(rm0, fmaxf(S[nf][0], S[nf][1]));
            rm1 = fmaxf(rm1, fmaxf(S[nf][2], S[nf][3]));
        }
        rm0 = fmaxf(rm0, __shfl_xor_sync(0xffffffff, rm0, 1));
        rm0 = fmaxf(rm0, __shfl_xor_sync(0xffffffff, rm0, 2));
        rm1 = fmaxf(rm1, __shfl_xor_sync(0xffffffff, rm1, 1));
        rm1 = fmaxf(rm1, __shfl_xor_sync(0xffffffff, rm1, 2));

        float mn0 = fmaxf(m0, rm0), mn1 = fmaxf(m1, rm1);
        float c0 = ex2f(m0 - mn0), c1 = ex2f(m1 - mn1);
        m0 = mn0; m1 = mn1;

        float rs0 = 0.f, rs1 = 0.f;
        #pragma unroll
        for (int nf = 0; nf < 8; nf++) {
            S[nf][0] = ex2f(S[nf][0] - m0);
            S[nf][1] = ex2f(S[nf][1] - m0);
            S[nf][2] = ex2f(S[nf][2] - m1);
            S[nf][3] = ex2f(S[nf][3] - m1);
            rs0 += S[nf][0] + S[nf][1];
            rs1 += S[nf][2] + S[nf][3];
        }
        rs0 += __shfl_xor_sync(0xffffffff, rs0, 1);
        rs0 += __shfl_xor_sync(0xffffffff, rs0, 2);
        rs1 += __shfl_xor_sync(0xffffffff, rs1, 1);
        rs1 += __shfl_xor_sync(0xffffffff, rs1, 2);
        l0 = l0 * c0 + rs0;
        l1 = l1 * c1 + rs1;

        #pragma unroll
        for (int nd = 0; nd < 8; nd++) {
            O[nd][0] *= c0; O[nd][1] *= c0;
            O[nd][2] *= c1; O[nd][3] *= c1;
        }

        // ---- O += P V (single-term fp16) ----
        #pragma unroll
        for (int kk = 0; kk < 4; kk++) {
            uint32_t Vf[4][4];
            #pragma unroll
            for (int gd = 0; gd < 4; gd++)
                ldsm_x4t(Vf[gd], sVf + SWZ128((kk * 16 + vRow) * 128 + gd * 32 + vKof));
            const float* p0 = S[2 * kk];
            const float* p1 = S[2 * kk + 1];
            uint32_t ah[4];
            ah[0] = pack_hf2(p0[0], p0[1]);
            ah[1] = pack_hf2(p0[2], p0[3]);
            ah[2] = pack_hf2(p1[0], p1[1]);
            ah[3] = pack_hf2(p1[2], p1[3]);
            #pragma unroll
            for (int nd = 0; nd < 8; nd++)
                mma_f16(O[nd], ah, &Vf[nd >> 1][(nd & 1) * 2]);
        }
    }

    const float inv0 = 1.f / l0, inv1 = 1.f / l1;
    const int b = hb >> 4, h = hb & 15;
    const size_t base0 = ((size_t)(b * SEQ + qg0)) * D_MODEL + h * D_HEAD;
    const size_t base1 = ((size_t)(b * SEQ + qg1)) * D_MODEL + h * D_HEAD;
    #pragma unroll
    for (int nd = 0; nd < 8; nd++) {
        int d = nd * 8 + (lane & 3) * 2;
        float v0 = O[nd][0] * inv0, v1 = O[nd][1] * inv0;
        float v2 = O[nd][2] * inv1, v3 = O[nd][3] * inv1;
        __nv_bfloat16 h0 = __float2bfloat16(v0), h1 = __float2bfloat16(v1);
        __nv_bfloat16 h2 = __float2bfloat16(v2), h3 = __float2bfloat16(v3);
        *(uint32_t*)&g_atthi[base0 + d] = pack_bf2(h0, h1);
        *(uint32_t*)&g_attlo[base0 + d] =
            pack_bf2(__float2bfloat16(v0 - __bfloat162float(h0)),
                     __float2bfloat16(v1 - __bfloat162float(h1)));
        *(uint32_t*)&g_atthi[base1 + d] = pack_bf2(h2, h3);
        *(uint32_t*)&g_attlo[base1 + d] =
            pack_bf2(__float2bfloat16(v2 - __bfloat162float(h2)),
                     __float2bfloat16(v3 - __bfloat162float(h3)));
    }
}

// ---------------------------------------------------------------------------
extern "C" void kernel_launch(void* const* d_in, const int* in_sizes, int n_in,
                              void* d_out, int out_size)
{
    const float* x     = (const float*)d_in[0];
    const float* W_qkv = (const float*)d_in[1];
    const float* W_out = (const float*)d_in[2];
    float* out = (float*)d_out;

    const int gemm_smem = 3 * STAGE_B3;                // 96 KB
    const int vgemm_smem = 3 * VSTAGE_B;               // 48 KB
    const int attn_smem = 2 * ATILE + 2 * KVST;        // 64 KB
    cudaFuncSetAttribute(qk_gemm_kernel,
                         cudaFuncAttributeMaxDynamicSharedMemorySize, gemm_smem);
    cudaFuncSetAttribute(out_gemm2_kernel,
                         cudaFuncAttributeMaxDynamicSharedMemorySize, gemm_smem);
    cudaFuncSetAttribute(v_gemm_kernel,
                         cudaFuncAttributeMaxDynamicSharedMemorySize, vgemm_smem);
    cudaFuncSetAttribute(attn_tc_kernel,
                         cudaFuncAttributeMaxDynamicSharedMemorySize, attn_smem);

    // 0) Input split / weight transposes
    {
        size_t n4 = (size_t)M_TOK * D_MODEL / 4;
        split_x_kernel<<<(unsigned)((n4 + 255) / 256), 256>>>(x);
        dim3 blk(32, 8);
        tr_wqkv_kernel<<<dim3(QKV_N / 32, D_MODEL / 32), blk>>>(W_qkv);
        tr_wout_kernel<<<dim3(D_MODEL / 32, D_MODEL / 32), blk>>>(W_out);
    }
    // 1a) q,k projection (3-term bf16 split) -> g_q{hi,lo}, g_k{hi,lo}
    qk_gemm_kernel<<<dim3(QK_N / 128, M_TOK / 128), 128, gemm_smem>>>();
    // 1b) v projection (single fp16) -> g_vf16
    v_gemm_kernel<<<dim3(D_MODEL / 128, M_TOK / 128), 128, vgemm_smem>>>();
    // 2) Causal flash attention -> g_att{hi,lo}
    attn_tc_kernel<<<dim3(AQT, HB), 128, attn_smem>>>();
    // 3) Output projection (3-term bf16 split) -> out
    out_gemm2_kernel<<<dim3(D_MODEL / 128, M_TOK / 128), 128, gemm_smem>>>(out);
}

// round 12
// speedup vs baseline: 1.9778x; 1.5553x over previous
#include <cuda_runtime.h>
#include <cuda_bf16.h>
#include <cuda_fp16.h>
#include <math.h>
#include <stdint.h>

#define D_MODEL 1024
#define N_HEADS 16
#define D_HEAD  64
#define BATCH   4
#define SEQ     2048
#define M_TOK   (BATCH * SEQ)     // 8192
#define QKV_N   (3 * D_MODEL)     // 3072
#define GK      1024
#define HB      (BATCH * N_HEADS) // 64

// ---------------------------------------------------------------------------
// Device-global scratch
// ---------------------------------------------------------------------------
__device__ __half        g_xf16[(size_t)M_TOK * D_MODEL];
__device__ __half        g_wqkvT_f16[(size_t)QKV_N * D_MODEL]; // [N][K]
__device__ __nv_bfloat16 g_woutT_hi[(size_t)D_MODEL * D_MODEL];
__device__ __nv_bfloat16 g_woutT_lo[(size_t)D_MODEL * D_MODEL];
// q/k/v single fp16, head-contiguous: [(b*16+h)][t][64]  (q pre-scaled)
__device__ __half        g_qf16[(size_t)HB * SEQ * D_HEAD];
__device__ __half        g_kf16[(size_t)HB * SEQ * D_HEAD];
__device__ __half        g_vf16[(size_t)HB * SEQ * D_HEAD];
// attention output, split bf16 (feeds 3-term out-proj)
__device__ __nv_bfloat16 g_atthi[(size_t)M_TOK * D_MODEL];
__device__ __nv_bfloat16 g_attlo[(size_t)M_TOK * D_MODEL];

// ---------------------------------------------------------------------------
// Baseline-PTX helpers (compute_103 target: no tcgen05)
// ---------------------------------------------------------------------------
__device__ __forceinline__ uint32_t smem_u32(const void* p) {
    uint32_t a;
    asm("{ .reg .u64 t; cvta.to.shared.u64 t, %1; cvt.u32.u64 %0, t; }"
        : "=r"(a) : "l"(p));
    return a;
}
__device__ __forceinline__ void cp16(uint32_t dst, const void* src) {
    asm volatile("cp.async.cg.shared.global [%0], [%1], 16;"
                 :: "r"(dst), "l"(src) : "memory");
}
#define CP_COMMIT() asm volatile("cp.async.commit_group;" ::: "memory")
#define CP_WAIT(n)  asm volatile("cp.async.wait_group %0;" :: "n"(n) : "memory")

__device__ __forceinline__ void ldsm_x4(uint32_t* r, uint32_t addr) {
    asm volatile("ldmatrix.sync.aligned.m8n8.x4.shared.b16 {%0,%1,%2,%3}, [%4];"
                 : "=r"(r[0]), "=r"(r[1]), "=r"(r[2]), "=r"(r[3]) : "r"(addr));
}
__device__ __forceinline__ void ldsm_x4t(uint32_t* r, uint32_t addr) {
    asm volatile("ldmatrix.sync.aligned.m8n8.x4.trans.shared.b16 {%0,%1,%2,%3}, [%4];"
                 : "=r"(r[0]), "=r"(r[1]), "=r"(r[2]), "=r"(r[3]) : "r"(addr));
}
__device__ __forceinline__ void mma_bf16(float* d, const uint32_t* a, const uint32_t* b) {
    asm volatile(
        "mma.sync.aligned.m16n8k16.row.col.f32.bf16.bf16.f32 "
        "{%0,%1,%2,%3}, {%4,%5,%6,%7}, {%8,%9}, {%0,%1,%2,%3};"
        : "+f"(d[0]), "+f"(d[1]), "+f"(d[2]), "+f"(d[3])
        : "r"(a[0]), "r"(a[1]), "r"(a[2]), "r"(a[3]), "r"(b[0]), "r"(b[1]));
}
__device__ __forceinline__ void mma_f16(float* d, const uint32_t* a, const uint32_t* b) {
    asm volatile(
        "mma.sync.aligned.m16n8k16.row.col.f32.f16.f16.f32 "
        "{%0,%1,%2,%3}, {%4,%5,%6,%7}, {%8,%9}, {%0,%1,%2,%3};"
        : "+f"(d[0]), "+f"(d[1]), "+f"(d[2]), "+f"(d[3])
        : "r"(a[0]), "r"(a[1]), "r"(a[2]), "r"(a[3]), "r"(b[0]), "r"(b[1]));
}
__device__ __forceinline__ float ex2f(float x) {
    float r;
    asm("ex2.approx.f32 %0, %1;" : "=f"(r) : "f"(x));
    return r;
}
#define SWZ128(o) ((o) ^ (((o) >> 3) & 0x70))
#define SWZ64(o)  ((o) ^ (((o) >> 3) & 0x30))

__device__ __forceinline__ uint32_t pack_bf2(__nv_bfloat16 a, __nv_bfloat16 b) {
    __nv_bfloat162 t(a, b);
    return *(uint32_t*)&t;
}
__device__ __forceinline__ uint32_t pack_hf2(float a, float b) {
    __half2 t = __floats2half2_rn(a, b);
    return *(uint32_t*)&t;
}

// q pre-scale folds 1/sqrt(64) AND log2(e): softmax runs in log2 domain.
#define Q_PRESCALE 0.180336880f

// ---------------------------------------------------------------------------
// Prep kernels
// ---------------------------------------------------------------------------
__global__ void conv_x_kernel(const float* __restrict__ x) {
    size_t i = ((size_t)blockIdx.x * blockDim.x + threadIdx.x) * 4;
    if (i >= (size_t)M_TOK * D_MODEL) return;
    float4 v = *(const float4*)(x + i);
    __half2* fp = (__half2*)(g_xf16 + i);
    fp[0] = __floats2half2_rn(v.x, v.y);
    fp[1] = __floats2half2_rn(v.z, v.w);
}

// W_qkv [K][N] -> fp16 T [N][K]
__global__ void tr_wqkv_f16_kernel(const float* __restrict__ W) {
    __shared__ float t[32][33];
    int tx = threadIdx.x, ty = threadIdx.y;
    int x = blockIdx.x * 32 + tx;
    int y0 = blockIdx.y * 32;
    #pragma unroll
    for (int j = 0; j < 32; j += 8)
        t[ty + j][tx] = W[(size_t)(y0 + ty + j) * QKV_N + x];
    __syncthreads();
    int xo = y0 + tx;
    int yo = blockIdx.x * 32;
    #pragma unroll
    for (int j = 0; j < 32; j += 8)
        g_wqkvT_f16[(size_t)(yo + ty + j) * GK + xo] = __float2half_rn(t[tx][ty + j]);
}

// W_out [K][N] -> split bf16 T hi/lo [N][K]
__global__ void tr_wout_kernel(const float* __restrict__ W) {
    __shared__ float t[32][33];
    int tx = threadIdx.x, ty = threadIdx.y;
    int x = blockIdx.x * 32 + tx;
    int y0 = blockIdx.y * 32;
    #pragma unroll
    for (int j = 0; j < 32; j += 8)
        t[ty + j][tx] = W[(size_t)(y0 + ty + j) * D_MODEL + x];
    __syncthreads();
    int xo = y0 + tx;
    int yo = blockIdx.x * 32;
    #pragma unroll
    for (int j = 0; j < 32; j += 8) {
        float v = t[tx][ty + j];
        __nv_bfloat16 h = __float2bfloat16(v);
        size_t o = (size_t)(yo + ty + j) * D_MODEL + xo;
        g_woutT_hi[o] = h;
        g_woutT_lo[o] = __float2bfloat16(v - __bfloat162float(h));
    }
}

// ---------------------------------------------------------------------------
// Shared GEMM tile machinery: CTA 128x128, 4 warps (64x64), KC=32 (SW64 rows)
// ---------------------------------------------------------------------------
#define KC       32
#define TILE_B3  (128 * 64)          // 8KB: 128 rows x 64B
#define NSTEPS3  (GK / KC)           // 32

__device__ __forceinline__ void tile_loads3(
    uint32_t sbase, const __nv_bfloat16* __restrict__ g, int k0, int tid)
{
    #pragma unroll
    for (int j = 0; j < 4; j++) {
        int i = tid + j * 128;            // 0..511 chunk id (16B chunks)
        int r = i >> 2, c = i & 3;
        cp16(sbase + SWZ64(r * 64 + c * 16), g + (size_t)r * GK + k0 + c * 8);
    }
}

// ---------------------------------------------------------------------------
// QKV GEMM: single-term fp16, N=3072. Epilogue split-writes q(prescaled)/k/v
// fp16 head-contiguous. 3-stage ring, 2 tiles/stage.
// ---------------------------------------------------------------------------
#define VSTAGE_B (2 * TILE_B3)       // 16KB: A,B

__global__ __launch_bounds__(128, 2) void qkv_f16_gemm_kernel()
{
    extern __shared__ char gsm[];
    const int tid  = threadIdx.x;
    const int wid  = tid >> 5, lane = tid & 31;
    const int cN   = blockIdx.x, cM = blockIdx.y;
    const int wm   = (wid & 1) * 64;
    const int wn   = (wid >> 1) * 64;

    const __nv_bfloat16* gA = (const __nv_bfloat16*)(g_xf16 + (size_t)cM * 128 * GK);
    const __nv_bfloat16* gB = (const __nv_bfloat16*)(g_wqkvT_f16 + (size_t)cN * 128 * GK);

    const uint32_t smbase = smem_u32(gsm);

    float acc[4][8][4];
    #pragma unroll
    for (int mi = 0; mi < 4; mi++)
        #pragma unroll
        for (int nf = 0; nf < 8; nf++)
            #pragma unroll
            for (int e = 0; e < 4; e++) acc[mi][nf][e] = 0.f;

    const int aRow = wm + (lane & 15);
    const int aKof = (lane >> 4) * 16;
    const int bRow = wn + ((lane >> 4) << 3) + (lane & 7);
    const int bKof = ((lane >> 3) & 1) * 16;

    tile_loads3(smbase,              gA, 0, tid);
    tile_loads3(smbase + TILE_B3,    gB, 0, tid);
    CP_COMMIT();
    tile_loads3(smbase + VSTAGE_B,           gA, KC, tid);
    tile_loads3(smbase + VSTAGE_B + TILE_B3, gB, KC, tid);
    CP_COMMIT();

    for (int kc = 0; kc < NSTEPS3; kc++) {
        const int slot = kc % 3;
        if (kc + 1 < NSTEPS3) { CP_WAIT(1); } else { CP_WAIT(0); }
        __syncthreads();
        if (kc + 2 < NSTEPS3) {
            uint32_t st = smbase + ((kc + 2) % 3) * VSTAGE_B;
            tile_loads3(st,           gA, (kc + 2) * KC, tid);
            tile_loads3(st + TILE_B3, gB, (kc + 2) * KC, tid);
            CP_COMMIT();
        }

        const uint32_t sA = smbase + slot * VSTAGE_B;
        const uint32_t sB = sA + TILE_B3;

        #pragma unroll
        for (int kk = 0; kk < 2; kk++) {
            const int kb = kk * 32;
            uint32_t a[4][4], b[4][4];
            #pragma unroll
            for (int mi = 0; mi < 4; mi++)
                ldsm_x4(a[mi], sA + SWZ64((aRow + mi * 16) * 64 + kb + aKof));
            #pragma unroll
            for (int g = 0; g < 4; g++)
                ldsm_x4(b[g], sB + SWZ64((bRow + g * 16) * 64 + kb + bKof));
            #pragma unroll
            for (int mi = 0; mi < 4; mi++)
                #pragma unroll
                for (int nf = 0; nf < 8; nf++)
                    mma_f16(acc[mi][nf], a[mi], &b[nf >> 1][(nf & 1) * 2]);
        }
    }

    // Epilogue: fp16 split-write q/k/v head-contiguous
    const int row0 = cM * 128 + wm + (lane >> 2);
    const int col0 = cN * 128 + wn + (lane & 3) * 2;
    #pragma unroll
    for (int mi = 0; mi < 4; mi++)
        #pragma unroll
        for (int nf = 0; nf < 8; nf++) {
            int c = col0 + nf * 8;
            int which = c >> 10;              // 0=q, 1=k, 2=v
            int h = (c >> 6) & 15;
            int d = c & 63;
            __half* dst = (which == 0) ? g_qf16 : (which == 1) ? g_kf16 : g_vf16;
            float sc = (which == 0) ? Q_PRESCALE : 1.f;
            #pragma unroll
            for (int rr = 0; rr < 2; rr++) {
                int r = row0 + mi * 16 + rr * 8;
                int b = r >> 11, t = r & 2047;
                size_t off = (((size_t)((b << 4) + h) << 11) + (size_t)t) * D_HEAD + d;
                *(uint32_t*)&dst[off] =
                    pack_hf2(acc[mi][nf][rr * 2] * sc, acc[mi][nf][rr * 2 + 1] * sc);
            }
        }
}

// ---------------------------------------------------------------------------
// Out-proj GEMM: 3-term split-bf16 (proven config). A = g_att{hi,lo},
// B = g_woutT{hi,lo}. 3-stage ring, 4 tiles/stage.
// ---------------------------------------------------------------------------
#define STAGE_B3 (4 * TILE_B3)       // 32KB

__global__ __launch_bounds__(128, 2) void out_gemm2_kernel(float* __restrict__ out)
{
    extern __shared__ char gsm[];
    const int tid  = threadIdx.x;
    const int wid  = tid >> 5, lane = tid & 31;
    const int cN   = blockIdx.x, cM = blockIdx.y;
    const int wm   = (wid & 1) * 64;
    const int wn   = (wid >> 1) * 64;

    const __nv_bfloat16* gAh = g_atthi + (size_t)cM * 128 * GK;
    const __nv_bfloat16* gAl = g_attlo + (size_t)cM * 128 * GK;
    const __nv_bfloat16* gBh = g_woutT_hi + (size_t)cN * 128 * GK;
    const __nv_bfloat16* gBl = g_woutT_lo + (size_t)cN * 128 * GK;

    const uint32_t smbase = smem_u32(gsm);

    float acc[4][8][4];
    #pragma unroll
    for (int mi = 0; mi < 4; mi++)
        #pragma unroll
        for (int nf = 0; nf < 8; nf++)
            #pragma unroll
            for (int e = 0; e < 4; e++) acc[mi][nf][e] = 0.f;

    const int aRow = wm + (lane & 15);
    const int aKof = (lane >> 4) * 16;
    const int bRow = wn + ((lane >> 4) << 3) + (lane & 7);
    const int bKof = ((lane >> 3) & 1) * 16;

    #pragma unroll
    for (int s = 0; s < 2; s++) {
        uint32_t st = smbase + s * STAGE_B3;
        tile_loads3(st + 0 * TILE_B3, gAh, s * KC, tid);
        tile_loads3(st + 1 * TILE_B3, gAl, s * KC, tid);
        tile_loads3(st + 2 * TILE_B3, gBh, s * KC, tid);
        tile_loads3(st + 3 * TILE_B3, gBl, s * KC, tid);
        CP_COMMIT();
    }

    for (int kc = 0; kc < NSTEPS3; kc++) {
        const int slot = kc % 3;
        if (kc + 1 < NSTEPS3) { CP_WAIT(1); } else { CP_WAIT(0); }
        __syncthreads();
        if (kc + 2 < NSTEPS3) {
            uint32_t st = smbase + ((kc + 2) % 3) * STAGE_B3;
            tile_loads3(st + 0 * TILE_B3, gAh, (kc + 2) * KC, tid);
            tile_loads3(st + 1 * TILE_B3, gAl, (kc + 2) * KC, tid);
            tile_loads3(st + 2 * TILE_B3, gBh, (kc + 2) * KC, tid);
            tile_loads3(st + 3 * TILE_B3, gBl, (kc + 2) * KC, tid);
            CP_COMMIT();
        }

        const uint32_t sAh = smbase + slot * STAGE_B3;
        const uint32_t sAl = sAh + TILE_B3;
        const uint32_t sBh = sAh + 2 * TILE_B3;
        const uint32_t sBl = sAh + 3 * TILE_B3;

        #pragma unroll
        for (int kk = 0; kk < 2; kk++) {
            const int kb = kk * 32;
            uint32_t aH[4][4], aL[4][4], bH[4][4], bL[4][4];
            #pragma unroll
            for (int mi = 0; mi < 4; mi++) {
                uint32_t off = SWZ64((aRow + mi * 16) * 64 + kb + aKof);
                ldsm_x4(aH[mi], sAh + off);
                ldsm_x4(aL[mi], sAl + off);
            }
            #pragma unroll
            for (int g = 0; g < 4; g++) {
                uint32_t off = SWZ64((bRow + g * 16) * 64 + kb + bKof);
                ldsm_x4(bH[g], sBh + off);
                ldsm_x4(bL[g], sBl + off);
            }
            #pragma unroll
            for (int mi = 0; mi < 4; mi++)
                #pragma unroll
                for (int nf = 0; nf < 8; nf++) {
                    const uint32_t* bh = &bH[nf >> 1][(nf & 1) * 2];
                    const uint32_t* bl = &bL[nf >> 1][(nf & 1) * 2];
                    mma_bf16(acc[mi][nf], aH[mi], bh);
                    mma_bf16(acc[mi][nf], aH[mi], bl);
                    mma_bf16(acc[mi][nf], aL[mi], bh);
                }
        }
    }

    const int row0 = cM * 128 + wm + (lane >> 2);
    const int col0 = cN * 128 + wn + (lane & 3) * 2;
    #pragma unroll
    for (int mi = 0; mi < 4; mi++)
        #pragma unroll
        for (int nf = 0; nf < 8; nf++) {
            int r = row0 + mi * 16;
            int c = col0 + nf * 8;
            float* c0 = out + (size_t)r * D_MODEL + c;
            float* c1 = c0 + 8 * D_MODEL;
            *(float2*)c0 = make_float2(acc[mi][nf][0], acc[mi][nf][1]);
            *(float2*)c1 = make_float2(acc[mi][nf][2], acc[mi][nf][3]);
        }
}

// ---------------------------------------------------------------------------
// Tensor-core causal flash attention: all-fp16 single-term S and PV.
// CTA: 128 thr = 4 warps, 64 q rows (16/warp), BK=64 keys/iter, 2-stage KV,
// log2-domain softmax.
// ---------------------------------------------------------------------------
#define AQ     64
#define AK     64
#define ATILE  8192                 // 64 rows x 128B
#define AQT    (SEQ / AQ)           // 32
#define KVST   (2 * ATILE)          // stage: Kf16, Vf16

__device__ __forceinline__ void load_tile64(
    uint32_t sbase, const void* __restrict__ g, int tid)
{
    #pragma unroll
    for (int j = 0; j < 4; j++) {
        int i = tid + j * 128;
        int r = i >> 3, c = i & 7;
        cp16(sbase + SWZ128(r * 128 + c * 16),
             (const __half*)g + (size_t)r * D_HEAD + c * 8);
    }
}
__device__ __forceinline__ void load_kv_stage(uint32_t st, size_t nb, int tid)
{
    load_tile64(st + 0 * ATILE, g_kf16 + nb, tid);
    load_tile64(st + 1 * ATILE, g_vf16 + nb, tid);
}

__global__ __launch_bounds__(128) void attn_tc_kernel()
{
    extern __shared__ char s_raw[];
    const int tid  = threadIdx.x;
    const int lane = tid & 31, wid = tid >> 5;
    const int qt = (AQT - 1) - blockIdx.x;   // long CTAs first
    const int hb = blockIdx.y;
    const int q0 = qt * AQ;
    const int wm = wid * 16;

    const uint32_t sb  = smem_u32(s_raw);
    const uint32_t sQ  = sb;
    const uint32_t sKV = sb + ATILE;         // 2 stages x {Kf16, Vf16}

    const size_t headBase = (size_t)hb * SEQ * D_HEAD;

    // Prologue: Q and stage0 K/V
    load_tile64(sQ, g_qf16 + headBase + (size_t)q0 * D_HEAD, tid);
    CP_COMMIT();
    load_kv_stage(sKV, headBase, tid);
    CP_COMMIT();
    CP_WAIT(0);
    __syncthreads();

    const int aRow = wm + (lane & 15);
    const int aKof = (lane >> 4) * 16;
    uint32_t Qf[4][4];
    #pragma unroll
    for (int kk = 0; kk < 4; kk++)
        ldsm_x4(Qf[kk], sQ + SWZ128(aRow * 128 + kk * 32 + aKof));

    const int bRow = ((lane >> 4) << 3) + (lane & 7);
    const int bKof = ((lane >> 3) & 1) * 16;
    const int vRow = lane & 15;
    const int vKof = (lane >> 4) * 16;

    float O[8][4];
    #pragma unroll
    for (int nd = 0; nd < 8; nd++)
        #pragma unroll
        for (int e = 0; e < 4; e++) O[nd][e] = 0.f;
    float m0 = -1e30f, m1 = -1e30f, l0 = 0.f, l1 = 0.f;

    const int qg0 = q0 + wm + (lane >> 2);
    const int qg1 = qg0 + 8;

    for (int kb = 0; kb <= q0; kb += AK) {
        const int stage = (kb >> 6) & 1;
        if (kb > 0) {
            CP_WAIT(0);
            __syncthreads();
        }
        if (kb + AK <= q0) {     // prefetch next stage
            load_kv_stage(sKV + (stage ^ 1) * KVST,
                          headBase + (size_t)(kb + AK) * D_HEAD, tid);
            CP_COMMIT();
        }

        const uint32_t sK = sKV + stage * KVST;
        const uint32_t sV = sK + ATILE;

        // ---- S = Q K^T (single fp16), log2 domain ----
        float S[8][4];
        #pragma unroll
        for (int nf = 0; nf < 8; nf++)
            #pragma unroll
            for (int e = 0; e < 4; e++) S[nf][e] = 0.f;

        #pragma unroll
        for (int kk = 0; kk < 4; kk++) {
            uint32_t Kf[4][4];
            #pragma unroll
            for (int g = 0; g < 4; g++)
                ldsm_x4(Kf[g], sK + SWZ128((bRow + g * 16) * 128 + kk * 32 + bKof));
            #pragma unroll
            for (int nf = 0; nf < 8; nf++)
                mma_f16(S[nf], Qf[kk], &Kf[nf >> 1][(nf & 1) * 2]);
        }

        if (kb == q0) {              // causal mask on diagonal tile
            #pragma unroll
            for (int nf = 0; nf < 8; nf++) {
                int kg = kb + nf * 8 + (lane & 3) * 2;
                if (kg     > qg0) S[nf][0] = -1e30f;
                if (kg + 1 > qg0) S[nf][1] = -1e30f;
                if (kg     > qg1) S[nf][2] = -1e30f;
                if (kg + 1 > qg1) S[nf][3] = -1e30f;
            }
        }

        // ---- online softmax (log2 domain) ----
        float rm0 = -1e30f, rm1 = -1e30f;
        #pragma unroll
        for (int nf = 0; nf < 8; nf++) {
            rm0 = fmaxf(rm0, fmaxf(S[nf][0], S[nf][1]));
            rm1 = fmaxf(rm1, fmaxf(S[nf][2], S[nf][3]));
        }
        rm0 = fmaxf(rm0, __shfl_xor_sync(0xffffffff, rm0, 1));
        rm0 = fmaxf(rm0, __shfl_xor_sync(0xffffffff, rm0, 2));
        rm1 = fmaxf(rm1, __shfl_xor_sync(0xffffffff, rm1, 1));
        rm1 = fmaxf(rm1, __shfl_xor_sync(0xffffffff, rm1, 2));

        float mn0 = fmaxf(m0, rm0), mn1 = fmaxf(m1, rm1);
        float c0 = ex2f(m0 - mn0), c1 = ex2f(m1 - mn1);
        m0 = mn0; m1 = mn1;

        float rs0 = 0.f, rs1 = 0.f;
        #pragma unroll
        for (int nf = 0; nf < 8; nf++) {
            S[nf][0] = ex2f(S[nf][0] - m0);
            S[nf][1] = ex2f(S[nf][1] - m0);
            S[nf][2] = ex2f(S[nf][2] - m1);
            S[nf][3] = ex2f(S[nf][3] - m1);
            rs0 += S[nf][0] + S[nf][1];
            rs1 += S[nf][2] + S[nf][3];
        }
        rs0 += __shfl_xor_sync(0xffffffff, rs0, 1);
        rs0 += __shfl_xor_sync(0xffffffff, rs0, 2);
        rs1 += __shfl_xor_sync(0xffffffff, rs1, 1);
        rs1 += __shfl_xor_sync(0xffffffff, rs1, 2);
        l0 = l0 * c0 + rs0;
        l1 = l1 * c1 + rs1;

        #pragma unroll
        for (int nd = 0; nd < 8; nd++) {
            O[nd][0] *= c0; O[nd][1] *= c0;
            O[nd][2] *= c1; O[nd][3] *= c1;
        }

        // ---- O += P V (single fp16) ----
        #pragma unroll
        for (int kk = 0; kk < 4; kk++) {
            uint32_t Vf[4][4];
            #pragma unroll
            for (int gd = 0; gd < 4; gd++)
                ldsm_x4t(Vf[gd], sV + SWZ128((kk * 16 + vRow) * 128 + gd * 32 + vKof));
            const float* p0 = S[2 * kk];
            const float* p1 = S[2 * kk + 1];
            uint32_t ah[4];
            ah[0] = pack_hf2(p0[0], p0[1]);
            ah[1] = pack_hf2(p0[2], p0[3]);
            ah[2] = pack_hf2(p1[0], p1[1]);
            ah[3] = pack_hf2(p1[2], p1[3]);
            #pragma unroll
            for (int nd = 0; nd < 8; nd++)
                mma_f16(O[nd], ah, &Vf[nd >> 1][(nd & 1) * 2]);
        }
    }

    const float inv0 = 1.f / l0, inv1 = 1.f / l1;
    const int b = hb >> 4, h = hb & 15;
    const size_t base0 = ((size_t)(b * SEQ + qg0)) * D_MODEL + h * D_HEAD;
    const size_t base1 = ((size_t)(b * SEQ + qg1)) * D_MODEL + h * D_HEAD;
    #pragma unroll
    for (int nd = 0; nd < 8; nd++) {
        int d = nd * 8 + (lane & 3) * 2;
        float v0 = O[nd][0] * inv0, v1 = O[nd][1] * inv0;
        float v2 = O[nd][2] * inv1, v3 = O[nd][3] * inv1;
        __nv_bfloat16 h0 = __float2bfloat16(v0), h1 = __float2bfloat16(v1);
        __nv_bfloat16 h2 = __float2bfloat16(v2), h3 = __float2bfloat16(v3);
        *(uint32_t*)&g_atthi[base0 + d] = pack_bf2(h0, h1);
        *(uint32_t*)&g_attlo[base0 + d] =
            pack_bf2(__float2bfloat16(v0 - __bfloat162float(h0)),
                     __float2bfloat16(v1 - __bfloat162float(h1)));
        *(uint32_t*)&g_atthi[base1 + d] = pack_bf2(h2, h3);
        *(uint32_t*)&g_attlo[base1 + d] =
            pack_bf2(__float2bfloat16(v2 - __bfloat162float(h2)),
                     __float2bfloat16(v3 - __bfloat162float(h3)));
    }
}

// ---------------------------------------------------------------------------
extern "C" void kernel_launch(void* const* d_in, const int* in_sizes, int n_in,
                              void* d_out, int out_size)
{
    const float* x     = (const float*)d_in[0];
    const float* W_qkv = (const float*)d_in[1];
    const float* W_out = (const float*)d_in[2];
    float* out = (float*)d_out;

    const int qkv_smem  = 3 * VSTAGE_B;           // 48 KB
    const int outg_smem = 3 * STAGE_B3;           // 96 KB
    const int attn_smem = ATILE + 2 * KVST;       // 40 KB
    cudaFuncSetAttribute(qkv_f16_gemm_kernel,
                         cudaFuncAttributeMaxDynamicSharedMemorySize, qkv_smem);
    cudaFuncSetAttribute(out_gemm2_kernel,
                         cudaFuncAttributeMaxDynamicSharedMemorySize, outg_smem);
    cudaFuncSetAttribute(attn_tc_kernel,
                         cudaFuncAttributeMaxDynamicSharedMemorySize, attn_smem);

    // 0) Input conversion / weight transposes
    {
        size_t n4 = (size_t)M_TOK * D_MODEL / 4;
        conv_x_kernel<<<(unsigned)((n4 + 255) / 256), 256>>>(x);
        dim3 blk(32, 8);
        tr_wqkv_f16_kernel<<<dim3(QKV_N / 32, D_MODEL / 32), blk>>>(W_qkv);
        tr_wout_kernel<<<dim3(D_MODEL / 32, D_MODEL / 32), blk>>>(W_out);
    }
    // 1) QKV projection (single fp16) -> q/k/v fp16 head-contiguous
    qkv_f16_gemm_kernel<<<dim3(QKV_N / 128, M_TOK / 128), 128, qkv_smem>>>();
    // 2) Causal flash attention (fp16 S and PV) -> g_att{hi,lo}
    attn_tc_kernel<<<dim3(AQT, HB), 128, attn_smem>>>();
    // 3) Output projection (3-term bf16 split) -> out
    out_gemm2_kernel<<<dim3(D_MODEL / 128, M_TOK / 128), 128, outg_smem>>>(out);
}

// round 15
// speedup vs baseline: 2.4787x; 1.2533x over previous
#include <cuda_runtime.h>
#include <cuda_fp16.h>
#include <math.h>
#include <stdint.h>

#define D_MODEL 1024
#define N_HEADS 16
#define D_HEAD  64
#define BATCH   4
#define SEQ     2048
#define M_TOK   (BATCH * SEQ)     // 8192
#define QKV_N   (3 * D_MODEL)     // 3072
#define GK      1024
#define HB      (BATCH * N_HEADS) // 64

// ---------------------------------------------------------------------------
// Device-global scratch (~58 MB total; no allocations anywhere)
// ---------------------------------------------------------------------------
__device__ __half g_xf16[(size_t)M_TOK * D_MODEL];
__device__ __half g_wqkvT_f16[(size_t)QKV_N * D_MODEL];   // [N][K]
__device__ __half g_woutT_f16[(size_t)D_MODEL * D_MODEL]; // [N][K]
// q/k/v single fp16, head-contiguous: [(b*16+h)][t][64]  (q pre-scaled)
__device__ __half g_qf16[(size_t)HB * SEQ * D_HEAD];
__device__ __half g_kf16[(size_t)HB * SEQ * D_HEAD];
__device__ __half g_vf16[(size_t)HB * SEQ * D_HEAD];
// attention output, single fp16 [token][h*64+d]
__device__ __half g_attf16[(size_t)M_TOK * D_MODEL];

// ---------------------------------------------------------------------------
// Baseline-PTX helpers (compute_103 target: no tcgen05)
// ---------------------------------------------------------------------------
__device__ __forceinline__ uint32_t smem_u32(const void* p) {
    uint32_t a;
    asm("{ .reg .u64 t; cvta.to.shared.u64 t, %1; cvt.u32.u64 %0, t; }"
        : "=r"(a) : "l"(p));
    return a;
}
__device__ __forceinline__ void cp16(uint32_t dst, const void* src) {
    asm volatile("cp.async.cg.shared.global [%0], [%1], 16;"
                 :: "r"(dst), "l"(src) : "memory");
}
#define CP_COMMIT() asm volatile("cp.async.commit_group;" ::: "memory")
#define CP_WAIT(n)  asm volatile("cp.async.wait_group %0;" :: "n"(n) : "memory")

__device__ __forceinline__ void ldsm_x4(uint32_t* r, uint32_t addr) {
    asm volatile("ldmatrix.sync.aligned.m8n8.x4.shared.b16 {%0,%1,%2,%3}, [%4];"
                 : "=r"(r[0]), "=r"(r[1]), "=r"(r[2]), "=r"(r[3]) : "r"(addr));
}
__device__ __forceinline__ void ldsm_x4t(uint32_t* r, uint32_t addr) {
    asm volatile("ldmatrix.sync.aligned.m8n8.x4.trans.shared.b16 {%0,%1,%2,%3}, [%4];"
                 : "=r"(r[0]), "=r"(r[1]), "=r"(r[2]), "=r"(r[3]) : "r"(addr));
}
__device__ __forceinline__ void mma_f16(float* d, const uint32_t* a, const uint32_t* b) {
    asm volatile(
        "mma.sync.aligned.m16n8k16.row.col.f32.f16.f16.f32 "
        "{%0,%1,%2,%3}, {%4,%5,%6,%7}, {%8,%9}, {%0,%1,%2,%3};"
        : "+f"(d[0]), "+f"(d[1]), "+f"(d[2]), "+f"(d[3])
        : "r"(a[0]), "r"(a[1]), "r"(a[2]), "r"(a[3]), "r"(b[0]), "r"(b[1]));
}
__device__ __forceinline__ float ex2f(float x) {
    float r;
    asm("ex2.approx.f32 %0, %1;" : "=f"(r) : "f"(x));
    return r;
}
#define SWZ128(o) ((o) ^ (((o) >> 3) & 0x70))
#define SWZ64(o)  ((o) ^ (((o) >> 3) & 0x30))

__device__ __forceinline__ uint32_t pack_hf2(float a, float b) {
    __half2 t = __floats2half2_rn(a, b);
    return *(uint32_t*)&t;
}

// q pre-scale folds 1/sqrt(64) AND log2(e): softmax runs in log2 domain.
#define Q_PRESCALE 0.180336880f

// ---------------------------------------------------------------------------
// Prep kernels
// ---------------------------------------------------------------------------
__global__ void conv_x_kernel(const float* __restrict__ x) {
    size_t i = ((size_t)blockIdx.x * blockDim.x + threadIdx.x) * 4;
    if (i >= (size_t)M_TOK * D_MODEL) return;
    float4 v = *(const float4*)(x + i);
    __half2* fp = (__half2*)(g_xf16 + i);
    fp[0] = __floats2half2_rn(v.x, v.y);
    fp[1] = __floats2half2_rn(v.z, v.w);
}

// W [K][N] -> fp16 T [N][K]
__device__ __forceinline__ void tr_f16_body(
    const float* __restrict__ W, __half* __restrict__ T, int N)
{
    __shared__ float t[32][33];
    int tx = threadIdx.x, ty = threadIdx.y;
    int x = blockIdx.x * 32 + tx;
    int y0 = blockIdx.y * 32;
    #pragma unroll
    for (int j = 0; j < 32; j += 8)
        t[ty + j][tx] = W[(size_t)(y0 + ty + j) * N + x];
    __syncthreads();
    int xo = y0 + tx;
    int yo = blockIdx.x * 32;
    #pragma unroll
    for (int j = 0; j < 32; j += 8)
        T[(size_t)(yo + ty + j) * GK + xo] = __float2half_rn(t[tx][ty + j]);
}
__global__ void tr_wqkv_f16_kernel(const float* __restrict__ W) {
    tr_f16_body(W, g_wqkvT_f16, QKV_N);
}
__global__ void tr_wout_f16_kernel(const float* __restrict__ W) {
    tr_f16_body(W, g_woutT_f16, D_MODEL);
}

// ---------------------------------------------------------------------------
// Shared GEMM tile machinery: CTA 128x128, 4 warps (64x64), KC=32 (SW64 rows)
// ---------------------------------------------------------------------------
#define KC       32
#define TILE_B3  (128 * 64)          // 8KB: 128 rows x 64B
#define NSTEPS3  (GK / KC)           // 32
#define VSTAGE_B (2 * TILE_B3)       // 16KB: A,B

__device__ __forceinline__ void tile_loads3(
    uint32_t sbase, const __half* __restrict__ g, int k0, int tid)
{
    #pragma unroll
    for (int j = 0; j < 4; j++) {
        int i = tid + j * 128;            // 0..511 chunk id (16B chunks)
        int r = i >> 2, c = i & 3;
        cp16(sbase + SWZ64(r * 64 + c * 16), g + (size_t)r * GK + k0 + c * 8);
    }
}

// ---------------------------------------------------------------------------
// Single-term fp16 GEMM body: 3-stage ring, 2 tiles/stage.
// MODE 0: write fp32 C[M][1024]. MODE 1: split-write q/k/v fp16 head-contig.
// ---------------------------------------------------------------------------
template <int MODE>
__device__ __forceinline__ void f16_gemm_body(
    const __half* __restrict__ A, const __half* __restrict__ B,
    float* __restrict__ C)
{
    extern __shared__ char gsm[];
    const int tid  = threadIdx.x;
    const int wid  = tid >> 5, lane = tid & 31;
    const int cN   = blockIdx.x, cM = blockIdx.y;
    const int wm   = (wid & 1) * 64;
    const int wn   = (wid >> 1) * 64;

    const __half* gA = A + (size_t)cM * 128 * GK;
    const __half* gB = B + (size_t)cN * 128 * GK;

    const uint32_t smbase = smem_u32(gsm);

    float acc[4][8][4];
    #pragma unroll
    for (int mi = 0; mi < 4; mi++)
        #pragma unroll
        for (int nf = 0; nf < 8; nf++)
            #pragma unroll
            for (int e = 0; e < 4; e++) acc[mi][nf][e] = 0.f;

    const int aRow = wm + (lane & 15);
    const int aKof = (lane >> 4) * 16;
    const int bRow = wn + ((lane >> 4) << 3) + (lane & 7);
    const int bKof = ((lane >> 3) & 1) * 16;

    tile_loads3(smbase,              gA, 0, tid);
    tile_loads3(smbase + TILE_B3,    gB, 0, tid);
    CP_COMMIT();
    tile_loads3(smbase + VSTAGE_B,           gA, KC, tid);
    tile_loads3(smbase + VSTAGE_B + TILE_B3, gB, KC, tid);
    CP_COMMIT();

    for (int kc = 0; kc < NSTEPS3; kc++) {
        const int slot = kc % 3;
        if (kc + 1 < NSTEPS3) { CP_WAIT(1); } else { CP_WAIT(0); }
        __syncthreads();
        if (kc + 2 < NSTEPS3) {
            uint32_t st = smbase + ((kc + 2) % 3) * VSTAGE_B;
            tile_loads3(st,           gA, (kc + 2) * KC, tid);
            tile_loads3(st + TILE_B3, gB, (kc + 2) * KC, tid);
            CP_COMMIT();
        }

        const uint32_t sA = smbase + slot * VSTAGE_B;
        const uint32_t sB = sA + TILE_B3;

        #pragma unroll
        for (int kk = 0; kk < 2; kk++) {
            const int kb = kk * 32;
            uint32_t a[4][4], b[4][4];
            #pragma unroll
            for (int mi = 0; mi < 4; mi++)
                ldsm_x4(a[mi], sA + SWZ64((aRow + mi * 16) * 64 + kb + aKof));
            #pragma unroll
            for (int g = 0; g < 4; g++)
                ldsm_x4(b[g], sB + SWZ64((bRow + g * 16) * 64 + kb + bKof));
            #pragma unroll
            for (int mi = 0; mi < 4; mi++)
                #pragma unroll
                for (int nf = 0; nf < 8; nf++)
                    mma_f16(acc[mi][nf], a[mi], &b[nf >> 1][(nf & 1) * 2]);
        }
    }

    const int row0 = cM * 128 + wm + (lane >> 2);
    const int col0 = cN * 128 + wn + (lane & 3) * 2;
    #pragma unroll
    for (int mi = 0; mi < 4; mi++)
        #pragma unroll
        for (int nf = 0; nf < 8; nf++) {
            int c = col0 + nf * 8;
            if (MODE == 0) {
                int r = row0 + mi * 16;
                float* c0 = C + (size_t)r * D_MODEL + c;
                float* c1 = c0 + 8 * D_MODEL;
                *(float2*)c0 = make_float2(acc[mi][nf][0], acc[mi][nf][1]);
                *(float2*)c1 = make_float2(acc[mi][nf][2], acc[mi][nf][3]);
            } else {
                int which = c >> 10;              // 0=q, 1=k, 2=v
                int h = (c >> 6) & 15;
                int d = c & 63;
                __half* dst = (which == 0) ? g_qf16 : (which == 1) ? g_kf16 : g_vf16;
                float sc = (which == 0) ? Q_PRESCALE : 1.f;
                #pragma unroll
                for (int rr = 0; rr < 2; rr++) {
                    int r = row0 + mi * 16 + rr * 8;
                    int b = r >> 11, t = r & 2047;
                    size_t off = (((size_t)((b << 4) + h) << 11) + (size_t)t) * D_HEAD + d;
                    *(uint32_t*)&dst[off] =
                        pack_hf2(acc[mi][nf][rr * 2] * sc, acc[mi][nf][rr * 2 + 1] * sc);
                }
            }
        }
}

__global__ __launch_bounds__(128, 2) void qkv_f16_gemm_kernel() {
    f16_gemm_body<1>(g_xf16, g_wqkvT_f16, nullptr);
}
__global__ __launch_bounds__(128, 2) void out_f16_gemm_kernel(float* __restrict__ out) {
    f16_gemm_body<0>(g_attf16, g_woutT_f16, out);
}

// ---------------------------------------------------------------------------
// Tensor-core causal flash attention: all-fp16 single-term S and PV.
// CTA: 128 thr = 4 warps, 64 q rows (16/warp), BK=64 keys/iter, 2-stage KV,
// log2-domain softmax. Output: single fp16.
// ---------------------------------------------------------------------------
#define AQ     64
#define AK     64
#define ATILE  8192                 // 64 rows x 128B
#define AQT    (SEQ / AQ)           // 32
#define KVST   (2 * ATILE)          // stage: Kf16, Vf16

__device__ __forceinline__ void load_tile64(
    uint32_t sbase, const __half* __restrict__ g, int tid)
{
    #pragma unroll
    for (int j = 0; j < 4; j++) {
        int i = tid + j * 128;
        int r = i >> 3, c = i & 7;
        cp16(sbase + SWZ128(r * 128 + c * 16), g + (size_t)r * D_HEAD + c * 8);
    }
}
__device__ __forceinline__ void load_kv_stage(uint32_t st, size_t nb, int tid)
{
    load_tile64(st + 0 * ATILE, g_kf16 + nb, tid);
    load_tile64(st + 1 * ATILE, g_vf16 + nb, tid);
}

__global__ __launch_bounds__(128) void attn_tc_kernel()
{
    extern __shared__ char s_raw[];
    const int tid  = threadIdx.x;
    const int lane = tid & 31, wid = tid >> 5;
    const int qt = (AQT - 1) - blockIdx.x;   // long CTAs first
    const int hb = blockIdx.y;
    const int q0 = qt * AQ;
    const int wm = wid * 16;

    const uint32_t sb  = smem_u32(s_raw);
    const uint32_t sQ  = sb;
    const uint32_t sKV = sb + ATILE;         // 2 stages x {Kf16, Vf16}

    const size_t headBase = (size_t)hb * SEQ * D_HEAD;

    load_tile64(sQ, g_qf16 + headBase + (size_t)q0 * D_HEAD, tid);
    CP_COMMIT();
    load_kv_stage(sKV, headBase, tid);
    CP_COMMIT();
    CP_WAIT(0);
    __syncthreads();

    const int aRow = wm + (lane & 15);
    const int aKof = (lane >> 4) * 16;
    uint32_t Qf[4][4];
    #pragma unroll
    for (int kk = 0; kk < 4; kk++)
        ldsm_x4(Qf[kk], sQ + SWZ128(aRow * 128 + kk * 32 + aKof));

    const int bRow = ((lane >> 4) << 3) + (lane & 7);
    const int bKof = ((lane >> 3) & 1) * 16;
    const int vRow = lane & 15;
    const int vKof = (lane >> 4) * 16;

    float O[8][4];
    #pragma unroll
    for (int nd = 0; nd < 8; nd++)
        #pragma unroll
        for (int e = 0; e < 4; e++) O[nd][e] = 0.f;
    float m0 = -1e30f, m1 = -1e30f, l0 = 0.f, l1 = 0.f;

    const int qg0 = q0 + wm + (lane >> 2);
    const int qg1 = qg0 + 8;

    for (int kb = 0; kb <= q0; kb += AK) {
        const int stage = (kb >> 6) & 1;
        if (kb > 0) {
            CP_WAIT(0);
            __syncthreads();
        }
        if (kb + AK <= q0) {
            load_kv_stage(sKV + (stage ^ 1) * KVST,
                          headBase + (size_t)(kb + AK) * D_HEAD, tid);
            CP_COMMIT();
        }

        const uint32_t sK = sKV + stage * KVST;
        const uint32_t sV = sK + ATILE;

        // ---- S = Q K^T (single fp16), log2 domain ----
        float S[8][4];
        #pragma unroll
        for (int nf = 0; nf < 8; nf++)
            #pragma unroll
            for (int e = 0; e < 4; e++) S[nf][e] = 0.f;

        #pragma unroll
        for (int kk = 0; kk < 4; kk++) {
            uint32_t Kf[4][4];
            #pragma unroll
            for (int g = 0; g < 4; g++)
                ldsm_x4(Kf[g], sK + SWZ128((bRow + g * 16) * 128 + kk * 32 + bKof));
            #pragma unroll
            for (int nf = 0; nf < 8; nf++)
                mma_f16(S[nf], Qf[kk], &Kf[nf >> 1][(nf & 1) * 2]);
        }

        if (kb == q0) {              // causal mask on diagonal tile
            #pragma unroll
            for (int nf = 0; nf < 8; nf++) {
                int kg = kb + nf * 8 + (lane & 3) * 2;
                if (kg     > qg0) S[nf][0] = -1e30f;
                if (kg + 1 > qg0) S[nf][1] = -1e30f;
                if (kg     > qg1) S[nf][2] = -1e30f;
                if (kg + 1 > qg1) S[nf][3] = -1e30f;
            }
        }

        // ---- online softmax (log2 domain) ----
        float rm0 = -1e30f, rm1 = -1e30f;
        #pragma unroll
        for (int nf = 0; nf < 8; nf++) {
            rm0 = fmaxf(rm0, fmaxf(S[nf][0], S[nf][1]));
            rm1 = fmaxf(rm1, fmaxf(S[nf][2], S[nf][3]));
        }
        rm0 = fmaxf(rm0, __shfl_xor_sync(0xffffffff, rm0, 1));
        rm0 = fmaxf(rm0, __shfl_xor_sync(0xffffffff, rm0, 2));
        rm1 = fmaxf(rm1, __shfl_xor_sync(0xffffffff, rm1, 1));
        rm1 = fmaxf(rm1, __shfl_xor_sync(0xffffffff, rm1, 2));

        float mn0 = fmaxf(m0, rm0), mn1 = fmaxf(m1, rm1);
        float c0 = ex2f(m0 - mn0), c1 = ex2f(m1 - mn1);
        m0 = mn0; m1 = mn1;

        float rs0 = 0.f, rs1 = 0.f;
        #pragma unroll
        for (int nf = 0; nf < 8; nf++) {
            S[nf][0] = ex2f(S[nf][0] - m0);
            S[nf][1] = ex2f(S[nf][1] - m0);
            S[nf][2] = ex2f(S[nf][2] - m1);
            S[nf][3] = ex2f(S[nf][3] - m1);
            rs0 += S[nf][0] + S[nf][1];
            rs1 += S[nf][2] + S[nf][3];
        }
        rs0 += __shfl_xor_sync(0xffffffff, rs0, 1);
        rs0 += __shfl_xor_sync(0xffffffff, rs0, 2);
        rs1 += __shfl_xor_sync(0xffffffff, rs1, 1);
        rs1 += __shfl_xor_sync(0xffffffff, rs1, 2);
        l0 = l0 * c0 + rs0;
        l1 = l1 * c1 + rs1;

        #pragma unroll
        for (int nd = 0; nd < 8; nd++) {
            O[nd][0] *= c0; O[nd][1] *= c0;
            O[nd][2] *= c1; O[nd][3] *= c1;
        }

        // ---- O += P V (single fp16) ----
        #pragma unroll
        for (int kk = 0; kk < 4; kk++) {
            uint32_t Vf[4][4];
            #pragma unroll
            for (int gd = 0; gd < 4; gd++)
                ldsm_x4t(Vf[gd], sV + SWZ128((kk * 16 + vRow) * 128 + gd * 32 + vKof));
            const float* p0 = S[2 * kk];
            const float* p1 = S[2 * kk + 1];
            uint32_t ah[4];
            ah[0] = pack_hf2(p0[0], p0[1]);
            ah[1] = pack_hf2(p0[2], p0[3]);
            ah[2] = pack_hf2(p1[0], p1[1]);
            ah[3] = pack_hf2(p1[2], p1[3]);
            #pragma unroll
            for (int nd = 0; nd < 8; nd++)
                mma_f16(O[nd], ah, &Vf[nd >> 1][(nd & 1) * 2]);
        }
    }

    // ---- epilogue: normalize, write single fp16 [token][h*64+d] ----
    const float inv0 = 1.f / l0, inv1 = 1.f / l1;
    const int b = hb >> 4, h = hb & 15;
    const size_t base0 = ((size_t)(b * SEQ + qg0)) * D_MODEL + h * D_HEAD;
    const size_t base1 = ((size_t)(b * SEQ + qg1)) * D_MODEL + h * D_HEAD;
    #pragma unroll
    for (int nd = 0; nd < 8; nd++) {
        int d = nd * 8 + (lane & 3) * 2;
        *(uint32_t*)&g_attf16[base0 + d] = pack_hf2(O[nd][0] * inv0, O[nd][1] * inv0);
        *(uint32_t*)&g_attf16[base1 + d] = pack_hf2(O[nd][2] * inv1, O[nd][3] * inv1);
    }
}

// ---------------------------------------------------------------------------
extern "C" void kernel_launch(void* const* d_in, const int* in_sizes, int n_in,
                              void* d_out, int out_size)
{
    const float* x     = (const float*)d_in[0];
    const float* W_qkv = (const float*)d_in[1];
    const float* W_out = (const float*)d_in[2];
    float* out = (float*)d_out;

    const int gemm_smem = 3 * VSTAGE_B;           // 48 KB
    const int attn_smem = ATILE + 2 * KVST;       // 40 KB
    cudaFuncSetAttribute(qkv_f16_gemm_kernel,
                         cudaFuncAttributeMaxDynamicSharedMemorySize, gemm_smem);
    cudaFuncSetAttribute(out_f16_gemm_kernel,
                         cudaFuncAttributeMaxDynamicSharedMemorySize, gemm_smem);
    cudaFuncSetAttribute(attn_tc_kernel,
                         cudaFuncAttributeMaxDynamicSharedMemorySize, attn_smem);

    // 0) Input conversion / weight transposes
    {
        size_t n4 = (size_t)M_TOK * D_MODEL / 4;
        conv_x_kernel<<<(unsigned)((n4 + 255) / 256), 256>>>(x);
        dim3 blk(32, 8);
        tr_wqkv_f16_kernel<<<dim3(QKV_N / 32, D_MODEL / 32), blk>>>(W_qkv);
        tr_wout_f16_kernel<<<dim3(D_MODEL / 32, D_MODEL / 32), blk>>>(W_out);
    }
    // 1) QKV projection (single fp16) -> q/k/v fp16 head-contiguous
    qkv_f16_gemm_kernel<<<dim3(QKV_N / 128, M_TOK / 128), 128, gemm_smem>>>();
    // 2) Causal flash attention (fp16) -> g_attf16
    attn_tc_kernel<<<dim3(AQT, HB), 128, attn_smem>>>();
    // 3) Output projection (single fp16) -> out (fp32)
    out_f16_gemm_kernel<<<dim3(D_MODEL / 128, M_TOK / 128), 128, gemm_smem>>>(out);
}